// round 14
// baseline (speedup 1.0000x reference)
#include <cuda_runtime.h>
#include <math.h>
#include <stdint.h>

// Problem constants
constexpr int B_   = 8;
constexpr int N_   = 1025;
constexpr int H_   = 12;
constexpr int HD_  = 64;
constexpr int DIM_ = 768;
constexpr int NTOK = B_ * N_;     // 8200
constexpr int C3   = 3 * DIM_;    // 2304
constexpr int BH   = B_ * H_;     // 96
constexpr float SCALE = 0.125f;

// Scratch (tf32-rounded-in-fp32 unless noted)
__device__ float g_Q[(size_t)BH * N_ * HD_];
__device__ float g_K[(size_t)BH * N_ * HD_];
__device__ float g_V[(size_t)BH * N_ * HD_];
__device__ float g_col0[BH * N_];              // fp32
__device__ float g_row0[BH * N_];              // fp32
__device__ float g_att[(size_t)NTOK * DIM_];
__device__ float g_xt[(size_t)NTOK * DIM_];
__device__ float g_wqkvt[C3 * DIM_];
__device__ float g_wprojt[DIM_ * DIM_];

// ---------------------------------------------------------------------------
__device__ __forceinline__ uint32_t f2tf(float f) {
    uint32_t u;
    asm("cvt.rna.tf32.f32 %0, %1;" : "=r"(u) : "f"(f));
    return u;
}

__device__ __forceinline__ void mma_tf32(float* d, const uint32_t* a, const uint32_t* b) {
    asm volatile(
        "mma.sync.aligned.m16n8k8.row.col.f32.tf32.tf32.f32 "
        "{%0,%1,%2,%3}, {%4,%5,%6,%7}, {%8,%9}, {%0,%1,%2,%3};\n"
        : "+f"(d[0]), "+f"(d[1]), "+f"(d[2]), "+f"(d[3])
        : "r"(a[0]), "r"(a[1]), "r"(a[2]), "r"(a[3]), "r"(b[0]), "r"(b[1]));
}

constexpr int LD   = 68;  // flash Q/K/P smem stride (words)
constexpr int LDV  = 72;  // flash V smem stride
constexpr int LDG_ = 36;  // GEMM smem stride (BK=32 + 4)

// ---------------------------------------------------------------------------
// Pre-round inputs to tf32 (once)
// ---------------------------------------------------------------------------
template <int W>
__global__ void precvt_kernel(const float* __restrict__ src, int n4) {
    int i = blockIdx.x * blockDim.x + threadIdx.x;
    if (i >= n4) return;
    float4 v = ((const float4*)src)[i];
    float* dst = (W == 0) ? g_xt : (W == 1) ? g_wqkvt : g_wprojt;
    ((uint4*)dst)[i] = make_uint4(f2tf(v.x), f2tf(v.y), f2tf(v.z), f2tf(v.w));
}

// ---------------------------------------------------------------------------
// tf32 GEMM (round-10 proven, 189 us): register prefetch + double-buffered
// smem, ONE sync per chunk. 256 threads = 8 warps (4x2), warp tile m32 x n64.
// ---------------------------------------------------------------------------
template <int MODE>
__global__ void __launch_bounds__(256, 2) gemm_tf32_kernel(const float* __restrict__ bias,
                                                           float* __restrict__ out,
                                                           int M) {
    extern __shared__ uint32_t gsm[];

    const uint32_t* A  = (MODE == 0) ? (const uint32_t*)g_xt   : (const uint32_t*)g_att;
    const uint32_t* Wm = (MODE == 0) ? (const uint32_t*)g_wqkvt : (const uint32_t*)g_wprojt;

    const int bm = blockIdx.y * 128;
    const int bn = blockIdx.x * 128;
    const int tid = threadIdx.x;
    const int warp = tid >> 5, lane = tid & 31;
    const int wr = warp >> 1, wc = warp & 1;
    const int g = lane >> 2, t = lane & 3;
    const int ar = wr * 32 + g;

    const int frow = tid >> 3;
    const int fcol = (tid & 7) << 2;

    float acc0[8][4], acc1[8][4];
    #pragma unroll
    for (int i = 0; i < 8; i++)
        #pragma unroll
        for (int j = 0; j < 4; j++) { acc0[i][j] = 0.f; acc1[i][j] = 0.f; }

    uint4 pa[4], pb[4];
    auto prefetch = [&](int k0) {
        #pragma unroll
        for (int r = 0; r < 4; r++) {
            int row = frow + 32 * r;
            int arow = min(bm + row, M - 1);
            pa[r] = *(const uint4*)&A[(size_t)arow * DIM_ + k0 + fcol];
            pb[r] = *(const uint4*)&Wm[(size_t)(bn + row) * DIM_ + k0 + fcol];
        }
    };

    prefetch(0);

    for (int kc = 0; kc < 24; kc++) {
        uint32_t* As = gsm + (kc & 1) * 4608;
        uint32_t* Bs = gsm + 9216 + (kc & 1) * 4608;

        #pragma unroll
        for (int r = 0; r < 4; r++) {
            int row = frow + 32 * r;
            *(uint4*)&As[row * LDG_ + fcol] = pa[r];
            *(uint4*)&Bs[row * LDG_ + fcol] = pb[r];
        }
        if (kc + 1 < 24) prefetch((kc + 1) * 32);
        __syncthreads();

        #pragma unroll
        for (int ks = 0; ks < 4; ks++) {
            const int kcc = ks * 8;
            uint32_t a0[4], a1[4];
            a0[0] = As[(ar +  0) * LDG_ + kcc + t];
            a0[1] = As[(ar +  8) * LDG_ + kcc + t];
            a0[2] = As[(ar +  0) * LDG_ + kcc + t + 4];
            a0[3] = As[(ar +  8) * LDG_ + kcc + t + 4];
            a1[0] = As[(ar + 16) * LDG_ + kcc + t];
            a1[1] = As[(ar + 24) * LDG_ + kcc + t];
            a1[2] = As[(ar + 16) * LDG_ + kcc + t + 4];
            a1[3] = As[(ar + 24) * LDG_ + kcc + t + 4];
            #pragma unroll
            for (int nt = 0; nt < 8; nt++) {
                uint32_t b[2];
                const int br = wc * 64 + nt * 8 + g;
                b[0] = Bs[br * LDG_ + kcc + t];
                b[1] = Bs[br * LDG_ + kcc + t + 4];
                mma_tf32(acc0[nt], a0, b);
                mma_tf32(acc1[nt], a1, b);
            }
        }
    }

    const int rows[4] = { bm + ar, bm + ar + 8, bm + ar + 16, bm + ar + 24 };
    #pragma unroll
    for (int nt = 0; nt < 8; nt++) {
        const int c0 = bn + wc * 64 + nt * 8 + 2 * t;
        float vals[4][2] = {
            {acc0[nt][0], acc0[nt][1]}, {acc0[nt][2], acc0[nt][3]},
            {acc1[nt][0], acc1[nt][1]}, {acc1[nt][2], acc1[nt][3]} };
        if (MODE == 0) {
            int which = c0 / DIM_;
            int rem = c0 - which * DIM_;
            int h = rem >> 6, d = rem & 63;
            float* dstf = (which == 0) ? g_Q : (which == 1) ? g_K : g_V;
            #pragma unroll
            for (int rr = 0; rr < 4; rr++) {
                int gm = rows[rr];
                if (gm < M) {
                    int b = gm / N_, n = gm - b * N_;
                    uint2 o = make_uint2(f2tf(vals[rr][0]), f2tf(vals[rr][1]));
                    *(uint2*)((uint32_t*)dstf +
                              (size_t)((b * H_ + h) * N_ + n) * HD_ + d) = o;
                }
            }
        } else {
            float bx = bias[c0], by = bias[c0 + 1];
            #pragma unroll
            for (int rr = 0; rr < 4; rr++) {
                int gm = rows[rr];
                if (gm < M) {
                    float2 o = make_float2(vals[rr][0] + bx, vals[rr][1] + by);
                    *(float2*)&out[(size_t)gm * DIM_ + c0] = o;
                }
            }
        }
    }
}

// ---------------------------------------------------------------------------
// cls scores (unroped, before rope)
// ---------------------------------------------------------------------------
__global__ void __launch_bounds__(256) cls_kernel() {
    int bh = blockIdx.x;
    int warp = threadIdx.x >> 5, lane = threadIdx.x & 31;
    int i = blockIdx.y * 8 + warp;
    if (i >= N_) return;
    const float2* Qi = (const float2*)(g_Q + ((size_t)bh * N_ + i) * HD_);
    const float2* K0 = (const float2*)(g_K + (size_t)bh * N_ * HD_);
    const float2* Q0 = (const float2*)(g_Q + (size_t)bh * N_ * HD_);
    const float2* Ki = (const float2*)(g_K + ((size_t)bh * N_ + i) * HD_);
    float2 a = Qi[lane], b0 = K0[lane], c = Q0[lane], d = Ki[lane];
    float s = a.x * b0.x + a.y * b0.y;
    float r = c.x * d.x + c.y * d.y;
    #pragma unroll
    for (int off = 16; off; off >>= 1) {
        s += __shfl_xor_sync(0xffffffffu, s, off);
        r += __shfl_xor_sync(0xffffffffu, r, off);
    }
    if (lane == 0) {
        g_col0[bh * N_ + i] = s;
        g_row0[bh * N_ + i] = r;
    }
}

// ---------------------------------------------------------------------------
// 2D RoPE in place on Q,K for n >= 1; outputs tf32-rounded
// ---------------------------------------------------------------------------
__global__ void rope_kernel(const int* __restrict__ xpos) {
    int b = blockIdx.x;
    int n = blockIdx.y + 1;
    int h = threadIdx.x >> 5;
    int lane = threadIdx.x & 31;
    int half = lane >> 4;
    int fi = lane & 15;
    float pos = (float)xpos[(b * N_ + n) * 2 + half];
    float inv = powf(100.f, -(float)fi / 16.f);
    float ang = pos * inv;
    float sv, cv;
    sincosf(ang, &sv, &cv);
    size_t base = ((size_t)(b * H_ + h) * N_ + n) * HD_ + half * 32;
    float t1 = g_Q[base + fi], t2 = g_Q[base + fi + 16];
    ((uint32_t*)g_Q)[base + fi]      = f2tf(t1 * cv - t2 * sv);
    ((uint32_t*)g_Q)[base + fi + 16] = f2tf(t2 * cv + t1 * sv);
    t1 = g_K[base + fi]; t2 = g_K[base + fi + 16];
    ((uint32_t*)g_K)[base + fi]      = f2tf(t1 * cv - t2 * sv);
    ((uint32_t*)g_K)[base + fi + 16] = f2tf(t2 * cv + t1 * sv);
}

// ---------------------------------------------------------------------------
// Flash attention main (round-11 proven structure, Q in smem): q rows
// 0..1023 only (grid.y = 8) -- all rows valid, guards removed.
// Tile-specialized overrides. Row 1024 handled by flash_last_kernel.
// ---------------------------------------------------------------------------
constexpr int FLASH_SMEM = (128 * LD + 64 * LD + 64 * LDV + 128 * LD) * 4;  // 105472

__global__ void __launch_bounds__(128) flash_tf32_kernel() {
    extern __shared__ uint32_t sm[];
    uint32_t* Qs = sm;                    // [128][LD]
    uint32_t* Ks = Qs + 128 * LD;         // [64][LD]
    uint32_t* Vs = Ks + 64 * LD;          // [64][LDV]
    uint32_t* Ps = Vs + 64 * LDV;         // [128][LD]

    const uint32_t* Qg = (const uint32_t*)g_Q;
    const uint32_t* Kg = (const uint32_t*)g_K;
    const uint32_t* Vg = (const uint32_t*)g_V;

    const int bh = blockIdx.x;
    const int qbase = blockIdx.y * 128;   // 0..896, all 128 rows valid
    const int tid = threadIdx.x;
    const int warp = tid >> 5, lane = tid & 31;
    const int g = lane >> 2, t = lane & 3;

    #pragma unroll
    for (int r = 0; r < 16; r++) {
        int idx = tid + 128 * r;
        int row = idx >> 4;
        int col = (idx & 15) << 2;
        *(uint4*)&Qs[row * LD + col] =
            *(const uint4*)&Qg[((size_t)bh * N_ + qbase + row) * HD_ + col];
    }

    float oacc0[8][4], oacc1[8][4];
    #pragma unroll
    for (int i = 0; i < 8; i++)
        #pragma unroll
        for (int j = 0; j < 4; j++) { oacc0[i][j] = 0.f; oacc1[i][j] = 0.f; }
    float m[4] = {-1e30f, -1e30f, -1e30f, -1e30f};
    float l[4] = {0.f, 0.f, 0.f, 0.f};

    const int pr0 = warp * 32 + g;
    const int rq[4] = { qbase + pr0, qbase + pr0 + 8,
                        qbase + pr0 + 16, qbase + pr0 + 24 };
    float colv[4];
    #pragma unroll
    for (int rr = 0; rr < 4; rr++) colv[rr] = g_col0[bh * N_ + rq[rr]];
    const bool qzero = (rq[0] == 0);
    const float* rowp = g_row0 + bh * N_;

    for (int kt = 0; kt < 1088; kt += 64) {
        __syncthreads();
        #pragma unroll
        for (int r = 0; r < 8; r++) {
            int idx = tid + 128 * r;
            int row = idx >> 4;
            int col = (idx & 15) << 2;
            int k = kt + row;
            uint4 kv = make_uint4(0u, 0u, 0u, 0u);
            uint4 vv = make_uint4(0u, 0u, 0u, 0u);
            if (k < N_) {
                kv = *(const uint4*)&Kg[((size_t)bh * N_ + k) * HD_ + col];
                vv = *(const uint4*)&Vg[((size_t)bh * N_ + k) * HD_ + col];
            }
            *(uint4*)&Ks[row * LD + col] = kv;
            *(uint4*)&Vs[row * LDV + col] = vv;
        }
        __syncthreads();

        float sacc0[8][4], sacc1[8][4];
        #pragma unroll
        for (int i = 0; i < 8; i++)
            #pragma unroll
            for (int j = 0; j < 4; j++) { sacc0[i][j] = 0.f; sacc1[i][j] = 0.f; }

        #pragma unroll
        for (int ks = 0; ks < 8; ks++) {
            const int kc = ks * 8;
            uint32_t a0[4], a1[4];
            a0[0] = Qs[(pr0 +  0) * LD + kc + t];
            a0[1] = Qs[(pr0 +  8) * LD + kc + t];
            a0[2] = Qs[(pr0 +  0) * LD + kc + t + 4];
            a0[3] = Qs[(pr0 +  8) * LD + kc + t + 4];
            a1[0] = Qs[(pr0 + 16) * LD + kc + t];
            a1[1] = Qs[(pr0 + 24) * LD + kc + t];
            a1[2] = Qs[(pr0 + 16) * LD + kc + t + 4];
            a1[3] = Qs[(pr0 + 24) * LD + kc + t + 4];
            #pragma unroll
            for (int nt = 0; nt < 8; nt++) {
                uint32_t b[2];
                const int br = nt * 8 + g;
                b[0] = Ks[br * LD + kc + t];
                b[1] = Ks[br * LD + kc + t + 4];
                mma_tf32(sacc0[nt], a0, b);
                mma_tf32(sacc1[nt], a1, b);
            }
        }

        // ---- tile-specialized overrides ----
        if (kt == 1024) {
            #pragma unroll
            for (int nt = 0; nt < 8; nt++)
                #pragma unroll
                for (int c = 0; c < 4; c++) {
                    int kcol = kt + nt * 8 + 2 * t + (c & 1);
                    if (kcol >= N_) { sacc0[nt][c] = -1e30f; sacc1[nt][c] = -1e30f; }
                }
        }
        if (kt == 0 && t == 0) {
            sacc0[0][0] = colv[0]; sacc0[0][2] = colv[1];
            sacc1[0][0] = colv[2]; sacc1[0][2] = colv[3];
        }
        if (qzero) {
            #pragma unroll
            for (int nt = 0; nt < 8; nt++)
                #pragma unroll
                for (int c = 0; c < 2; c++) {
                    int kcol = kt + nt * 8 + 2 * t + c;
                    if (kcol < N_) sacc0[nt][c] = rowp[kcol];
                }
        }
        #pragma unroll
        for (int nt = 0; nt < 8; nt++)
            #pragma unroll
            for (int c = 0; c < 4; c++) { sacc0[nt][c] *= SCALE; sacc1[nt][c] *= SCALE; }
        // ------------------------------------

        #pragma unroll
        for (int hh = 0; hh < 4; hh++) {
            float (*sa)[4] = (hh < 2) ? sacc0 : sacc1;
            float (*oa)[4] = (hh < 2) ? oacc0 : oacc1;
            const int co = (hh & 1) * 2;
            float mx = -1e30f;
            #pragma unroll
            for (int nt = 0; nt < 8; nt++)
                mx = fmaxf(mx, fmaxf(sa[nt][co], sa[nt][co + 1]));
            mx = fmaxf(mx, __shfl_xor_sync(0xffffffffu, mx, 1));
            mx = fmaxf(mx, __shfl_xor_sync(0xffffffffu, mx, 2));
            float mn = fmaxf(m[hh], mx);
            float corr = __expf(m[hh] - mn);
            m[hh] = mn;
            float ls = 0.f;
            #pragma unroll
            for (int nt = 0; nt < 8; nt++) {
                float p0 = __expf(sa[nt][co] - mn);
                float p1 = __expf(sa[nt][co + 1] - mn);
                ls += p0 + p1;
                sa[nt][co] = p0;
                sa[nt][co + 1] = p1;
            }
            l[hh] = l[hh] * corr + ls;
            #pragma unroll
            for (int nt = 0; nt < 8; nt++) {
                oa[nt][co] *= corr;
                oa[nt][co + 1] *= corr;
            }
        }

        #pragma unroll
        for (int nt = 0; nt < 8; nt++) {
            int kc = nt * 8 + 2 * t;
            *(uint2*)&Ps[(pr0 +  0) * LD + kc] = make_uint2(f2tf(sacc0[nt][0]), f2tf(sacc0[nt][1]));
            *(uint2*)&Ps[(pr0 +  8) * LD + kc] = make_uint2(f2tf(sacc0[nt][2]), f2tf(sacc0[nt][3]));
            *(uint2*)&Ps[(pr0 + 16) * LD + kc] = make_uint2(f2tf(sacc1[nt][0]), f2tf(sacc1[nt][1]));
            *(uint2*)&Ps[(pr0 + 24) * LD + kc] = make_uint2(f2tf(sacc1[nt][2]), f2tf(sacc1[nt][3]));
        }
        __syncwarp();

        #pragma unroll
        for (int ks = 0; ks < 8; ks++) {
            const int kc = ks * 8;
            uint32_t a0[4], a1[4];
            a0[0] = Ps[(pr0 +  0) * LD + kc + t];
            a0[1] = Ps[(pr0 +  8) * LD + kc + t];
            a0[2] = Ps[(pr0 +  0) * LD + kc + t + 4];
            a0[3] = Ps[(pr0 +  8) * LD + kc + t + 4];
            a1[0] = Ps[(pr0 + 16) * LD + kc + t];
            a1[1] = Ps[(pr0 + 24) * LD + kc + t];
            a1[2] = Ps[(pr0 + 16) * LD + kc + t + 4];
            a1[3] = Ps[(pr0 + 24) * LD + kc + t + 4];
            #pragma unroll
            for (int nt = 0; nt < 8; nt++) {
                uint32_t b[2];
                b[0] = Vs[(kc + t) * LDV + nt * 8 + g];
                b[1] = Vs[(kc + t + 4) * LDV + nt * 8 + g];
                mma_tf32(oacc0[nt], a0, b);
                mma_tf32(oacc1[nt], a1, b);
            }
        }
    }

    #pragma unroll
    for (int hh = 0; hh < 4; hh++) {
        l[hh] += __shfl_xor_sync(0xffffffffu, l[hh], 1);
        l[hh] += __shfl_xor_sync(0xffffffffu, l[hh], 2);
        l[hh] = 1.f / l[hh];
    }
    const int b = bh / H_, h = bh - b * H_;
    uint32_t* att = (uint32_t*)g_att;
    #pragma unroll
    for (int nt = 0; nt < 8; nt++) {
        int d = nt * 8 + 2 * t;
        float vals[4][2] = {
            {oacc0[nt][0], oacc0[nt][1]}, {oacc0[nt][2], oacc0[nt][3]},
            {oacc1[nt][0], oacc1[nt][1]}, {oacc1[nt][2], oacc1[nt][3]} };
        #pragma unroll
        for (int rr = 0; rr < 4; rr++) {
            uint2 o = make_uint2(f2tf(vals[rr][0] * l[rr]), f2tf(vals[rr][1] * l[rr]));
            *(uint2*)&att[((size_t)(b * N_ + rq[rr])) * DIM_ + h * HD_ + d] = o;
        }
    }
}

// ---------------------------------------------------------------------------
// Flash last row (q = 1024): one block per bh, fp32 scalar path.
// (validated in round 13; qs 16-aligned)
// ---------------------------------------------------------------------------
__global__ void __launch_bounds__(128) flash_last_kernel() {
    __shared__ __align__(16) float qs[64];
    __shared__ float red[128];
    __shared__ float sc[1025];

    const int bh = blockIdx.x;
    const int tid = threadIdx.x;

    const float* Qr = g_Q + ((size_t)bh * N_ + 1024) * HD_;
    if (tid < 16) *(float4*)&qs[tid * 4] = *(const float4*)&Qr[tid * 4];
    __syncthreads();

    for (int j = tid; j < N_; j += 128) {
        const float* kr = g_K + ((size_t)bh * N_ + j) * HD_;
        float s = 0.f;
        #pragma unroll
        for (int d = 0; d < 64; d += 4) {
            float4 kv = *(const float4*)&kr[d];
            s = fmaf(qs[d], kv.x, s);
            s = fmaf(qs[d + 1], kv.y, s);
            s = fmaf(qs[d + 2], kv.z, s);
            s = fmaf(qs[d + 3], kv.w, s);
        }
        if (j == 0) s = g_col0[bh * N_ + 1024];
        sc[j] = s * SCALE;
    }
    __syncthreads();

    float mx = -1e30f;
    for (int j = tid; j < N_; j += 128) mx = fmaxf(mx, sc[j]);
    red[tid] = mx;
    __syncthreads();
    #pragma unroll
    for (int s = 64; s > 0; s >>= 1) {
        if (tid < s) red[tid] = fmaxf(red[tid], red[tid + s]);
        __syncthreads();
    }
    mx = red[0];
    __syncthreads();

    float ls = 0.f;
    for (int j = tid; j < N_; j += 128) {
        float p = __expf(sc[j] - mx);
        sc[j] = p;
        ls += p;
    }
    red[tid] = ls;
    __syncthreads();
    #pragma unroll
    for (int s = 64; s > 0; s >>= 1) {
        if (tid < s) red[tid] += red[tid + s];
        __syncthreads();
    }
    const float linv = 1.f / red[0];
    __syncthreads();

    if (tid < 64) {
        float acc = 0.f;
        const float* vbase = g_V + (size_t)bh * N_ * HD_ + tid;
        #pragma unroll 8
        for (int j = 0; j < N_; j++)
            acc = fmaf(sc[j], vbase[(size_t)j * HD_], acc);
        const int b = bh / H_, h = bh - b * H_;
        ((uint32_t*)g_att)[((size_t)(b * N_ + 1024)) * DIM_ + h * HD_ + tid] =
            f2tf(acc * linv);
    }
}

// ---------------------------------------------------------------------------
constexpr int GEMM_SMEM = 4 * 4608 * 4;   // 73728

extern "C" void kernel_launch(void* const* d_in, const int* in_sizes, int n_in,
                              void* d_out, int out_size) {
    int ix = -1, ixpos = -1, iwqkv = -1, iwproj = -1, ibproj = -1;
    for (int k = 0; k < n_in; k++) {
        switch (in_sizes[k]) {
            case NTOK * DIM_:  ix = k; break;
            case NTOK * 2:     ixpos = k; break;
            case C3 * DIM_:    iwqkv = k; break;
            case DIM_ * DIM_:  iwproj = k; break;
            case DIM_:         ibproj = k; break;
            default: break;
        }
    }
    const float* x      = (const float*)d_in[ix];
    const int*   xpos   = (const int*)d_in[ixpos];
    const float* w_qkv  = (const float*)d_in[iwqkv];
    const float* w_proj = (const float*)d_in[iwproj];
    const float* b_proj = (const float*)d_in[ibproj];
    float* out = (float*)d_out;

    cudaFuncSetAttribute(gemm_tf32_kernel<0>, cudaFuncAttributeMaxDynamicSharedMemorySize, GEMM_SMEM);
    cudaFuncSetAttribute(gemm_tf32_kernel<1>, cudaFuncAttributeMaxDynamicSharedMemorySize, GEMM_SMEM);
    cudaFuncSetAttribute(flash_tf32_kernel,   cudaFuncAttributeMaxDynamicSharedMemorySize, FLASH_SMEM);

    const int mtiles = (NTOK + 127) / 128;   // 65

    precvt_kernel<0><<<(NTOK * DIM_ / 4 + 255) / 256, 256>>>(x, NTOK * DIM_ / 4);
    precvt_kernel<1><<<(C3 * DIM_ / 4 + 255) / 256, 256>>>(w_qkv, C3 * DIM_ / 4);
    precvt_kernel<2><<<(DIM_ * DIM_ / 4 + 255) / 256, 256>>>(w_proj, DIM_ * DIM_ / 4);

    gemm_tf32_kernel<0><<<dim3(C3 / 128, mtiles), 256, GEMM_SMEM>>>(nullptr, nullptr, NTOK);
    cls_kernel<<<dim3(BH, (N_ + 7) / 8), 256>>>();
    rope_kernel<<<dim3(B_, N_ - 1), H_ * 32>>>(xpos);
    flash_tf32_kernel<<<dim3(BH, 8), 128, FLASH_SMEM>>>();
    flash_last_kernel<<<BH, 128>>>();
    gemm_tf32_kernel<1><<<dim3(DIM_ / 128, mtiles), 256, GEMM_SMEM>>>(b_proj, out, NTOK);
}

// round 15
// speedup vs baseline: 1.0294x; 1.0294x over previous
#include <cuda_runtime.h>
#include <math.h>
#include <stdint.h>

// Problem constants
constexpr int B_   = 8;
constexpr int N_   = 1025;
constexpr int H_   = 12;
constexpr int HD_  = 64;
constexpr int DIM_ = 768;
constexpr int NTOK = B_ * N_;     // 8200
constexpr int C3   = 3 * DIM_;    // 2304
constexpr int BH   = B_ * H_;     // 96
constexpr float SCALE = 0.125f;

// Scratch (tf32-rounded-in-fp32 unless noted)
__device__ float g_Q[(size_t)BH * N_ * HD_];
__device__ float g_K[(size_t)BH * N_ * HD_];
__device__ float g_V[(size_t)BH * N_ * HD_];
__device__ float g_col0[BH * N_];              // fp32
__device__ float g_row0[BH * N_];              // fp32
__device__ float g_att[(size_t)NTOK * DIM_];
__device__ float g_xt[(size_t)NTOK * DIM_];
__device__ float g_wqkvt[C3 * DIM_];
__device__ float g_wprojt[DIM_ * DIM_];

// ---------------------------------------------------------------------------
__device__ __forceinline__ uint32_t f2tf(float f) {
    uint32_t u;
    asm("cvt.rna.tf32.f32 %0, %1;" : "=r"(u) : "f"(f));
    return u;
}

__device__ __forceinline__ void mma_tf32(float* d, const uint32_t* a, const uint32_t* b) {
    asm volatile(
        "mma.sync.aligned.m16n8k8.row.col.f32.tf32.tf32.f32 "
        "{%0,%1,%2,%3}, {%4,%5,%6,%7}, {%8,%9}, {%0,%1,%2,%3};\n"
        : "+f"(d[0]), "+f"(d[1]), "+f"(d[2]), "+f"(d[3])
        : "r"(a[0]), "r"(a[1]), "r"(a[2]), "r"(a[3]), "r"(b[0]), "r"(b[1]));
}

constexpr int LD   = 68;  // flash Q/K/P smem stride (words)
constexpr int LDV  = 72;  // flash V smem stride
constexpr int LDG_ = 36;  // GEMM smem stride (BK=32 + 4)

// ---------------------------------------------------------------------------
// Pre-round inputs to tf32 (once)
// ---------------------------------------------------------------------------
template <int W>
__global__ void precvt_kernel(const float* __restrict__ src, int n4) {
    int i = blockIdx.x * blockDim.x + threadIdx.x;
    if (i >= n4) return;
    float4 v = ((const float4*)src)[i];
    float* dst = (W == 0) ? g_xt : (W == 1) ? g_wqkvt : g_wprojt;
    ((uint4*)dst)[i] = make_uint4(f2tf(v.x), f2tf(v.y), f2tf(v.z), f2tf(v.w));
}

// ---------------------------------------------------------------------------
// tf32 GEMM (round-10 proven, 189 us): register prefetch + double-buffered
// smem, ONE sync per chunk. 256 threads = 8 warps (4x2), warp tile m32 x n64.
// ---------------------------------------------------------------------------
template <int MODE>
__global__ void __launch_bounds__(256, 2) gemm_tf32_kernel(const float* __restrict__ bias,
                                                           float* __restrict__ out,
                                                           int M) {
    extern __shared__ uint32_t gsm[];

    const uint32_t* A  = (MODE == 0) ? (const uint32_t*)g_xt   : (const uint32_t*)g_att;
    const uint32_t* Wm = (MODE == 0) ? (const uint32_t*)g_wqkvt : (const uint32_t*)g_wprojt;

    const int bm = blockIdx.y * 128;
    const int bn = blockIdx.x * 128;
    const int tid = threadIdx.x;
    const int warp = tid >> 5, lane = tid & 31;
    const int wr = warp >> 1, wc = warp & 1;
    const int g = lane >> 2, t = lane & 3;
    const int ar = wr * 32 + g;

    const int frow = tid >> 3;
    const int fcol = (tid & 7) << 2;

    float acc0[8][4], acc1[8][4];
    #pragma unroll
    for (int i = 0; i < 8; i++)
        #pragma unroll
        for (int j = 0; j < 4; j++) { acc0[i][j] = 0.f; acc1[i][j] = 0.f; }

    uint4 pa[4], pb[4];
    auto prefetch = [&](int k0) {
        #pragma unroll
        for (int r = 0; r < 4; r++) {
            int row = frow + 32 * r;
            int arow = min(bm + row, M - 1);
            pa[r] = *(const uint4*)&A[(size_t)arow * DIM_ + k0 + fcol];
            pb[r] = *(const uint4*)&Wm[(size_t)(bn + row) * DIM_ + k0 + fcol];
        }
    };

    prefetch(0);

    for (int kc = 0; kc < 24; kc++) {
        uint32_t* As = gsm + (kc & 1) * 4608;
        uint32_t* Bs = gsm + 9216 + (kc & 1) * 4608;

        #pragma unroll
        for (int r = 0; r < 4; r++) {
            int row = frow + 32 * r;
            *(uint4*)&As[row * LDG_ + fcol] = pa[r];
            *(uint4*)&Bs[row * LDG_ + fcol] = pb[r];
        }
        if (kc + 1 < 24) prefetch((kc + 1) * 32);
        __syncthreads();

        #pragma unroll
        for (int ks = 0; ks < 4; ks++) {
            const int kcc = ks * 8;
            uint32_t a0[4], a1[4];
            a0[0] = As[(ar +  0) * LDG_ + kcc + t];
            a0[1] = As[(ar +  8) * LDG_ + kcc + t];
            a0[2] = As[(ar +  0) * LDG_ + kcc + t + 4];
            a0[3] = As[(ar +  8) * LDG_ + kcc + t + 4];
            a1[0] = As[(ar + 16) * LDG_ + kcc + t];
            a1[1] = As[(ar + 24) * LDG_ + kcc + t];
            a1[2] = As[(ar + 16) * LDG_ + kcc + t + 4];
            a1[3] = As[(ar + 24) * LDG_ + kcc + t + 4];
            #pragma unroll
            for (int nt = 0; nt < 8; nt++) {
                uint32_t b[2];
                const int br = wc * 64 + nt * 8 + g;
                b[0] = Bs[br * LDG_ + kcc + t];
                b[1] = Bs[br * LDG_ + kcc + t + 4];
                mma_tf32(acc0[nt], a0, b);
                mma_tf32(acc1[nt], a1, b);
            }
        }
    }

    const int rows[4] = { bm + ar, bm + ar + 8, bm + ar + 16, bm + ar + 24 };
    #pragma unroll
    for (int nt = 0; nt < 8; nt++) {
        const int c0 = bn + wc * 64 + nt * 8 + 2 * t;
        float vals[4][2] = {
            {acc0[nt][0], acc0[nt][1]}, {acc0[nt][2], acc0[nt][3]},
            {acc1[nt][0], acc1[nt][1]}, {acc1[nt][2], acc1[nt][3]} };
        if (MODE == 0) {
            int which = c0 / DIM_;
            int rem = c0 - which * DIM_;
            int h = rem >> 6, d = rem & 63;
            float* dstf = (which == 0) ? g_Q : (which == 1) ? g_K : g_V;
            #pragma unroll
            for (int rr = 0; rr < 4; rr++) {
                int gm = rows[rr];
                if (gm < M) {
                    int b = gm / N_, n = gm - b * N_;
                    uint2 o = make_uint2(f2tf(vals[rr][0]), f2tf(vals[rr][1]));
                    *(uint2*)((uint32_t*)dstf +
                              (size_t)((b * H_ + h) * N_ + n) * HD_ + d) = o;
                }
            }
        } else {
            float bx = bias[c0], by = bias[c0 + 1];
            #pragma unroll
            for (int rr = 0; rr < 4; rr++) {
                int gm = rows[rr];
                if (gm < M) {
                    float2 o = make_float2(vals[rr][0] + bx, vals[rr][1] + by);
                    *(float2*)&out[(size_t)gm * DIM_ + c0] = o;
                }
            }
        }
    }
}

// ---------------------------------------------------------------------------
// cls scores (unroped, before rope)
// ---------------------------------------------------------------------------
__global__ void __launch_bounds__(256) cls_kernel() {
    int bh = blockIdx.x;
    int warp = threadIdx.x >> 5, lane = threadIdx.x & 31;
    int i = blockIdx.y * 8 + warp;
    if (i >= N_) return;
    const float2* Qi = (const float2*)(g_Q + ((size_t)bh * N_ + i) * HD_);
    const float2* K0 = (const float2*)(g_K + (size_t)bh * N_ * HD_);
    const float2* Q0 = (const float2*)(g_Q + (size_t)bh * N_ * HD_);
    const float2* Ki = (const float2*)(g_K + ((size_t)bh * N_ + i) * HD_);
    float2 a = Qi[lane], b0 = K0[lane], c = Q0[lane], d = Ki[lane];
    float s = a.x * b0.x + a.y * b0.y;
    float r = c.x * d.x + c.y * d.y;
    #pragma unroll
    for (int off = 16; off; off >>= 1) {
        s += __shfl_xor_sync(0xffffffffu, s, off);
        r += __shfl_xor_sync(0xffffffffu, r, off);
    }
    if (lane == 0) {
        g_col0[bh * N_ + i] = s;
        g_row0[bh * N_ + i] = r;
    }
}

// ---------------------------------------------------------------------------
// 2D RoPE in place on Q,K for n >= 1; outputs tf32-rounded
// ---------------------------------------------------------------------------
__global__ void rope_kernel(const int* __restrict__ xpos) {
    int b = blockIdx.x;
    int n = blockIdx.y + 1;
    int h = threadIdx.x >> 5;
    int lane = threadIdx.x & 31;
    int half = lane >> 4;
    int fi = lane & 15;
    float pos = (float)xpos[(b * N_ + n) * 2 + half];
    float inv = powf(100.f, -(float)fi / 16.f);
    float ang = pos * inv;
    float sv, cv;
    sincosf(ang, &sv, &cv);
    size_t base = ((size_t)(b * H_ + h) * N_ + n) * HD_ + half * 32;
    float t1 = g_Q[base + fi], t2 = g_Q[base + fi + 16];
    ((uint32_t*)g_Q)[base + fi]      = f2tf(t1 * cv - t2 * sv);
    ((uint32_t*)g_Q)[base + fi + 16] = f2tf(t2 * cv + t1 * sv);
    t1 = g_K[base + fi]; t2 = g_K[base + fi + 16];
    ((uint32_t*)g_K)[base + fi]      = f2tf(t1 * cv - t2 * sv);
    ((uint32_t*)g_K)[base + fi + 16] = f2tf(t2 * cv + t1 * sv);
}

// ---------------------------------------------------------------------------
// Flash attention main: q rows 0..1023 (grid.y = 8), round-11 structure
// + K/V register prefetch (GEMM-proven pattern): LDG for tile kt+64 issued
// during tile kt's compute. Same 2 barriers per tile.
// ---------------------------------------------------------------------------
constexpr int FLASH_SMEM = (128 * LD + 64 * LD + 64 * LDV + 128 * LD) * 4;  // 105472

__global__ void __launch_bounds__(128) flash_tf32_kernel() {
    extern __shared__ uint32_t sm[];
    uint32_t* Qs = sm;                    // [128][LD]
    uint32_t* Ks = Qs + 128 * LD;         // [64][LD]
    uint32_t* Vs = Ks + 64 * LD;          // [64][LDV]
    uint32_t* Ps = Vs + 64 * LDV;         // [128][LD]

    const uint32_t* Qg = (const uint32_t*)g_Q;
    const uint32_t* Kg = (const uint32_t*)g_K;
    const uint32_t* Vg = (const uint32_t*)g_V;

    const int bh = blockIdx.x;
    const int qbase = blockIdx.y * 128;   // 0..896, all rows valid
    const int tid = threadIdx.x;
    const int warp = tid >> 5, lane = tid & 31;
    const int g = lane >> 2, t = lane & 3;

    #pragma unroll
    for (int r = 0; r < 16; r++) {
        int idx = tid + 128 * r;
        int row = idx >> 4;
        int col = (idx & 15) << 2;
        *(uint4*)&Qs[row * LD + col] =
            *(const uint4*)&Qg[((size_t)bh * N_ + qbase + row) * HD_ + col];
    }

    // K/V register prefetch buffers (8 rows per thread x {K,V})
    uint4 pk[8], pv[8];
    auto prefetch_kv = [&](int kt) {
        #pragma unroll
        for (int r = 0; r < 8; r++) {
            int idx = tid + 128 * r;
            int row = idx >> 4;
            int col = (idx & 15) << 2;
            int k = kt + row;
            uint4 kv = make_uint4(0u, 0u, 0u, 0u);
            uint4 vv = make_uint4(0u, 0u, 0u, 0u);
            if (k < N_) {
                kv = *(const uint4*)&Kg[((size_t)bh * N_ + k) * HD_ + col];
                vv = *(const uint4*)&Vg[((size_t)bh * N_ + k) * HD_ + col];
            }
            pk[r] = kv;
            pv[r] = vv;
        }
    };
    prefetch_kv(0);

    float oacc0[8][4], oacc1[8][4];
    #pragma unroll
    for (int i = 0; i < 8; i++)
        #pragma unroll
        for (int j = 0; j < 4; j++) { oacc0[i][j] = 0.f; oacc1[i][j] = 0.f; }
    float m[4] = {-1e30f, -1e30f, -1e30f, -1e30f};
    float l[4] = {0.f, 0.f, 0.f, 0.f};

    const int pr0 = warp * 32 + g;
    const int rq[4] = { qbase + pr0, qbase + pr0 + 8,
                        qbase + pr0 + 16, qbase + pr0 + 24 };
    float colv[4];
    #pragma unroll
    for (int rr = 0; rr < 4; rr++) colv[rr] = g_col0[bh * N_ + rq[rr]];
    const bool qzero = (rq[0] == 0);
    const float* rowp = g_row0 + bh * N_;

    for (int kt = 0; kt < 1088; kt += 64) {
        __syncthreads();   // prior tile's reads of Ks/Vs complete
        #pragma unroll
        for (int r = 0; r < 8; r++) {
            int idx = tid + 128 * r;
            int row = idx >> 4;
            int col = (idx & 15) << 2;
            *(uint4*)&Ks[row * LD + col] = pk[r];
            *(uint4*)&Vs[row * LDV + col] = pv[r];
        }
        if (kt + 64 < 1088) prefetch_kv(kt + 64);   // LDGs fly during compute
        __syncthreads();

        float sacc0[8][4], sacc1[8][4];
        #pragma unroll
        for (int i = 0; i < 8; i++)
            #pragma unroll
            for (int j = 0; j < 4; j++) { sacc0[i][j] = 0.f; sacc1[i][j] = 0.f; }

        #pragma unroll
        for (int ks = 0; ks < 8; ks++) {
            const int kc = ks * 8;
            uint32_t a0[4], a1[4];
            a0[0] = Qs[(pr0 +  0) * LD + kc + t];
            a0[1] = Qs[(pr0 +  8) * LD + kc + t];
            a0[2] = Qs[(pr0 +  0) * LD + kc + t + 4];
            a0[3] = Qs[(pr0 +  8) * LD + kc + t + 4];
            a1[0] = Qs[(pr0 + 16) * LD + kc + t];
            a1[1] = Qs[(pr0 + 24) * LD + kc + t];
            a1[2] = Qs[(pr0 + 16) * LD + kc + t + 4];
            a1[3] = Qs[(pr0 + 24) * LD + kc + t + 4];
            #pragma unroll
            for (int nt = 0; nt < 8; nt++) {
                uint32_t b[2];
                const int br = nt * 8 + g;
                b[0] = Ks[br * LD + kc + t];
                b[1] = Ks[br * LD + kc + t + 4];
                mma_tf32(sacc0[nt], a0, b);
                mma_tf32(sacc1[nt], a1, b);
            }
        }

        // ---- tile-specialized overrides ----
        if (kt == 1024) {
            #pragma unroll
            for (int nt = 0; nt < 8; nt++)
                #pragma unroll
                for (int c = 0; c < 4; c++) {
                    int kcol = kt + nt * 8 + 2 * t + (c & 1);
                    if (kcol >= N_) { sacc0[nt][c] = -1e30f; sacc1[nt][c] = -1e30f; }
                }
        }
        if (kt == 0 && t == 0) {
            sacc0[0][0] = colv[0]; sacc0[0][2] = colv[1];
            sacc1[0][0] = colv[2]; sacc1[0][2] = colv[3];
        }
        if (qzero) {
            #pragma unroll
            for (int nt = 0; nt < 8; nt++)
                #pragma unroll
                for (int c = 0; c < 2; c++) {
                    int kcol = kt + nt * 8 + 2 * t + c;
                    if (kcol < N_) sacc0[nt][c] = rowp[kcol];
                }
        }
        #pragma unroll
        for (int nt = 0; nt < 8; nt++)
            #pragma unroll
            for (int c = 0; c < 4; c++) { sacc0[nt][c] *= SCALE; sacc1[nt][c] *= SCALE; }
        // ------------------------------------

        #pragma unroll
        for (int hh = 0; hh < 4; hh++) {
            float (*sa)[4] = (hh < 2) ? sacc0 : sacc1;
            float (*oa)[4] = (hh < 2) ? oacc0 : oacc1;
            const int co = (hh & 1) * 2;
            float mx = -1e30f;
            #pragma unroll
            for (int nt = 0; nt < 8; nt++)
                mx = fmaxf(mx, fmaxf(sa[nt][co], sa[nt][co + 1]));
            mx = fmaxf(mx, __shfl_xor_sync(0xffffffffu, mx, 1));
            mx = fmaxf(mx, __shfl_xor_sync(0xffffffffu, mx, 2));
            float mn = fmaxf(m[hh], mx);
            float corr = __expf(m[hh] - mn);
            m[hh] = mn;
            float ls = 0.f;
            #pragma unroll
            for (int nt = 0; nt < 8; nt++) {
                float p0 = __expf(sa[nt][co] - mn);
                float p1 = __expf(sa[nt][co + 1] - mn);
                ls += p0 + p1;
                sa[nt][co] = p0;
                sa[nt][co + 1] = p1;
            }
            l[hh] = l[hh] * corr + ls;
            #pragma unroll
            for (int nt = 0; nt < 8; nt++) {
                oa[nt][co] *= corr;
                oa[nt][co + 1] *= corr;
            }
        }

        #pragma unroll
        for (int nt = 0; nt < 8; nt++) {
            int kc = nt * 8 + 2 * t;
            *(uint2*)&Ps[(pr0 +  0) * LD + kc] = make_uint2(f2tf(sacc0[nt][0]), f2tf(sacc0[nt][1]));
            *(uint2*)&Ps[(pr0 +  8) * LD + kc] = make_uint2(f2tf(sacc0[nt][2]), f2tf(sacc0[nt][3]));
            *(uint2*)&Ps[(pr0 + 16) * LD + kc] = make_uint2(f2tf(sacc1[nt][0]), f2tf(sacc1[nt][1]));
            *(uint2*)&Ps[(pr0 + 24) * LD + kc] = make_uint2(f2tf(sacc1[nt][2]), f2tf(sacc1[nt][3]));
        }
        __syncwarp();

        #pragma unroll
        for (int ks = 0; ks < 8; ks++) {
            const int kc = ks * 8;
            uint32_t a0[4], a1[4];
            a0[0] = Ps[(pr0 +  0) * LD + kc + t];
            a0[1] = Ps[(pr0 +  8) * LD + kc + t];
            a0[2] = Ps[(pr0 +  0) * LD + kc + t + 4];
            a0[3] = Ps[(pr0 +  8) * LD + kc + t + 4];
            a1[0] = Ps[(pr0 + 16) * LD + kc + t];
            a1[1] = Ps[(pr0 + 24) * LD + kc + t];
            a1[2] = Ps[(pr0 + 16) * LD + kc + t + 4];
            a1[3] = Ps[(pr0 + 24) * LD + kc + t + 4];
            #pragma unroll
            for (int nt = 0; nt < 8; nt++) {
                uint32_t b[2];
                b[0] = Vs[(kc + t) * LDV + nt * 8 + g];
                b[1] = Vs[(kc + t + 4) * LDV + nt * 8 + g];
                mma_tf32(oacc0[nt], a0, b);
                mma_tf32(oacc1[nt], a1, b);
            }
        }
    }

    #pragma unroll
    for (int hh = 0; hh < 4; hh++) {
        l[hh] += __shfl_xor_sync(0xffffffffu, l[hh], 1);
        l[hh] += __shfl_xor_sync(0xffffffffu, l[hh], 2);
        l[hh] = 1.f / l[hh];
    }
    const int b = bh / H_, h = bh - b * H_;
    uint32_t* att = (uint32_t*)g_att;
    #pragma unroll
    for (int nt = 0; nt < 8; nt++) {
        int d = nt * 8 + 2 * t;
        float vals[4][2] = {
            {oacc0[nt][0], oacc0[nt][1]}, {oacc0[nt][2], oacc0[nt][3]},
            {oacc1[nt][0], oacc1[nt][1]}, {oacc1[nt][2], oacc1[nt][3]} };
        #pragma unroll
        for (int rr = 0; rr < 4; rr++) {
            uint2 o = make_uint2(f2tf(vals[rr][0] * l[rr]), f2tf(vals[rr][1] * l[rr]));
            *(uint2*)&att[((size_t)(b * N_ + rq[rr])) * DIM_ + h * HD_ + d] = o;
        }
    }
}

// ---------------------------------------------------------------------------
// Flash last row (q = 1024): 256 threads, PV parallelized 4-way over j.
// ---------------------------------------------------------------------------
__global__ void __launch_bounds__(256) flash_last_kernel() {
    __shared__ __align__(16) float qs[64];
    __shared__ float red[256];
    __shared__ float pvp[4][64];
    __shared__ float sc[1025];

    const int bh = blockIdx.x;
    const int tid = threadIdx.x;

    const float* Qr = g_Q + ((size_t)bh * N_ + 1024) * HD_;
    if (tid < 16) *(float4*)&qs[tid * 4] = *(const float4*)&Qr[tid * 4];
    __syncthreads();

    for (int j = tid; j < N_; j += 256) {
        const float* kr = g_K + ((size_t)bh * N_ + j) * HD_;
        float s = 0.f;
        #pragma unroll
        for (int d = 0; d < 64; d += 4) {
            float4 kv = *(const float4*)&kr[d];
            s = fmaf(qs[d], kv.x, s);
            s = fmaf(qs[d + 1], kv.y, s);
            s = fmaf(qs[d + 2], kv.z, s);
            s = fmaf(qs[d + 3], kv.w, s);
        }
        if (j == 0) s = g_col0[bh * N_ + 1024];
        sc[j] = s * SCALE;
    }
    __syncthreads();

    float mx = -1e30f;
    for (int j = tid; j < N_; j += 256) mx = fmaxf(mx, sc[j]);
    red[tid] = mx;
    __syncthreads();
    #pragma unroll
    for (int s = 128; s > 0; s >>= 1) {
        if (tid < s) red[tid] = fmaxf(red[tid], red[tid + s]);
        __syncthreads();
    }
    mx = red[0];
    __syncthreads();

    float ls = 0.f;
    for (int j = tid; j < N_; j += 256) {
        float p = __expf(sc[j] - mx);
        sc[j] = p;
        ls += p;
    }
    red[tid] = ls;
    __syncthreads();
    #pragma unroll
    for (int s = 128; s > 0; s >>= 1) {
        if (tid < s) red[tid] += red[tid + s];
        __syncthreads();
    }
    const float linv = 1.f / red[0];
    __syncthreads();

    // PV: thread = (slice, d); slice handles j = slice, slice+4, ...
    {
        const int d = tid & 63;
        const int sl = tid >> 6;           // 0..3
        float acc = 0.f;
        const float* vbase = g_V + (size_t)bh * N_ * HD_ + d;
        for (int j = sl; j < N_; j += 4)
            acc = fmaf(sc[j], vbase[(size_t)j * HD_], acc);
        pvp[sl][d] = acc;
    }
    __syncthreads();
    if (tid < 64) {
        float acc = ((pvp[0][tid] + pvp[1][tid]) + (pvp[2][tid] + pvp[3][tid])) * linv;
        const int b = bh / H_, h = bh - b * H_;
        ((uint32_t*)g_att)[((size_t)(b * N_ + 1024)) * DIM_ + h * HD_ + tid] = f2tf(acc);
    }
}

// ---------------------------------------------------------------------------
constexpr int GEMM_SMEM = 4 * 4608 * 4;   // 73728

extern "C" void kernel_launch(void* const* d_in, const int* in_sizes, int n_in,
                              void* d_out, int out_size) {
    int ix = -1, ixpos = -1, iwqkv = -1, iwproj = -1, ibproj = -1;
    for (int k = 0; k < n_in; k++) {
        switch (in_sizes[k]) {
            case NTOK * DIM_:  ix = k; break;
            case NTOK * 2:     ixpos = k; break;
            case C3 * DIM_:    iwqkv = k; break;
            case DIM_ * DIM_:  iwproj = k; break;
            case DIM_:         ibproj = k; break;
            default: break;
        }
    }
    const float* x      = (const float*)d_in[ix];
    const int*   xpos   = (const int*)d_in[ixpos];
    const float* w_qkv  = (const float*)d_in[iwqkv];
    const float* w_proj = (const float*)d_in[iwproj];
    const float* b_proj = (const float*)d_in[ibproj];
    float* out = (float*)d_out;

    cudaFuncSetAttribute(gemm_tf32_kernel<0>, cudaFuncAttributeMaxDynamicSharedMemorySize, GEMM_SMEM);
    cudaFuncSetAttribute(gemm_tf32_kernel<1>, cudaFuncAttributeMaxDynamicSharedMemorySize, GEMM_SMEM);
    cudaFuncSetAttribute(flash_tf32_kernel,   cudaFuncAttributeMaxDynamicSharedMemorySize, FLASH_SMEM);

    const int mtiles = (NTOK + 127) / 128;   // 65

    precvt_kernel<0><<<(NTOK * DIM_ / 4 + 255) / 256, 256>>>(x, NTOK * DIM_ / 4);
    precvt_kernel<1><<<(C3 * DIM_ / 4 + 255) / 256, 256>>>(w_qkv, C3 * DIM_ / 4);
    precvt_kernel<2><<<(DIM_ * DIM_ / 4 + 255) / 256, 256>>>(w_proj, DIM_ * DIM_ / 4);

    gemm_tf32_kernel<0><<<dim3(C3 / 128, mtiles), 256, GEMM_SMEM>>>(nullptr, nullptr, NTOK);
    cls_kernel<<<dim3(BH, (N_ + 7) / 8), 256>>>();
    rope_kernel<<<dim3(B_, N_ - 1), H_ * 32>>>(xpos);
    flash_tf32_kernel<<<dim3(BH, 8), 128, FLASH_SMEM>>>();
    flash_last_kernel<<<BH, 256>>>();
    gemm_tf32_kernel<1><<<dim3(DIM_ / 128, mtiles), 256, GEMM_SMEM>>>(b_proj, out, NTOK);
}

// round 16
// speedup vs baseline: 1.0907x; 1.0596x over previous
#include <cuda_runtime.h>
#include <math.h>
#include <stdint.h>

// Problem constants
constexpr int B_   = 8;
constexpr int N_   = 1025;
constexpr int H_   = 12;
constexpr int HD_  = 64;
constexpr int DIM_ = 768;
constexpr int NTOK = B_ * N_;     // 8200
constexpr int C3   = 3 * DIM_;    // 2304
constexpr int BH   = B_ * H_;     // 96
constexpr float SCALE = 0.125f;

// Scratch (tf32-rounded-in-fp32 unless noted)
__device__ float g_Q[(size_t)BH * N_ * HD_];
__device__ float g_K[(size_t)BH * N_ * HD_];
__device__ float g_V[(size_t)BH * N_ * HD_];
__device__ float g_col0[BH * N_];              // fp32
__device__ float g_row0[BH * N_];              // fp32
__device__ float g_att[(size_t)NTOK * DIM_];
__device__ float g_xt[(size_t)NTOK * DIM_];
__device__ float g_wqkvt[C3 * DIM_];
__device__ float g_wprojt[DIM_ * DIM_];

// ---------------------------------------------------------------------------
__device__ __forceinline__ uint32_t f2tf(float f) {
    uint32_t u;
    asm("cvt.rna.tf32.f32 %0, %1;" : "=r"(u) : "f"(f));
    return u;
}

__device__ __forceinline__ void mma_tf32(float* d, const uint32_t* a, const uint32_t* b) {
    asm volatile(
        "mma.sync.aligned.m16n8k8.row.col.f32.tf32.tf32.f32 "
        "{%0,%1,%2,%3}, {%4,%5,%6,%7}, {%8,%9}, {%0,%1,%2,%3};\n"
        : "+f"(d[0]), "+f"(d[1]), "+f"(d[2]), "+f"(d[3])
        : "r"(a[0]), "r"(a[1]), "r"(a[2]), "r"(a[3]), "r"(b[0]), "r"(b[1]));
}

constexpr int LD   = 68;  // flash Q/K/P smem stride (words)
constexpr int LDV  = 72;  // flash V smem stride
constexpr int LDG_ = 36;  // GEMM smem stride (BK=32 + 4)

// ---------------------------------------------------------------------------
// Pre-round inputs to tf32 (once)
// ---------------------------------------------------------------------------
template <int W>
__global__ void precvt_kernel(const float* __restrict__ src, int n4) {
    int i = blockIdx.x * blockDim.x + threadIdx.x;
    if (i >= n4) return;
    float4 v = ((const float4*)src)[i];
    float* dst = (W == 0) ? g_xt : (W == 1) ? g_wqkvt : g_wprojt;
    ((uint4*)dst)[i] = make_uint4(f2tf(v.x), f2tf(v.y), f2tf(v.z), f2tf(v.w));
}

// ---------------------------------------------------------------------------
// tf32 GEMM, templated on BM for wave-quantization fit.
// BMt=128: 8 warps as 4x2, warp m32 x n64 (round-10 proven config, MODE 0).
// BMt=64 : 8 warps as 2x4, warp m32 x n32 (MODE 1 -- 774 blocks vs 390,
//          fills 3 waves with half-size blocks instead of 2 ragged waves).
// Register prefetch + double-buffered smem, ONE sync per chunk.
// ---------------------------------------------------------------------------
template <int MODE, int BMt>
__global__ void __launch_bounds__(256, 2) gemm_tf32_kernel(const float* __restrict__ bias,
                                                           float* __restrict__ out,
                                                           int M) {
    extern __shared__ uint32_t gsm[];

    constexpr int NT = (BMt == 128) ? 8 : 4;   // n8-tiles per warp
    constexpr int RA = BMt / 32;               // A-fill quads per thread
    constexpr int ASZ = BMt * LDG_;            // A stage size (words)
    constexpr int BSZ = 128 * LDG_;            // B stage size

    const uint32_t* A  = (MODE == 0) ? (const uint32_t*)g_xt   : (const uint32_t*)g_att;
    const uint32_t* Wm = (MODE == 0) ? (const uint32_t*)g_wqkvt : (const uint32_t*)g_wprojt;

    const int bm = blockIdx.y * BMt;
    const int bn = blockIdx.x * 128;
    const int tid = threadIdx.x;
    const int warp = tid >> 5, lane = tid & 31;
    const int wr = (BMt == 128) ? (warp >> 1) : (warp >> 2);
    const int wc = (BMt == 128) ? (warp & 1) : (warp & 3);
    const int g = lane >> 2, t = lane & 3;
    const int ar = wr * 32 + g;

    const int frow = tid >> 3;            // 0..31
    const int fcol = (tid & 7) << 2;      // 0,4,...,28

    float acc0[NT][4], acc1[NT][4];
    #pragma unroll
    for (int i = 0; i < NT; i++)
        #pragma unroll
        for (int j = 0; j < 4; j++) { acc0[i][j] = 0.f; acc1[i][j] = 0.f; }

    uint4 pa[RA], pb[4];
    auto prefetch = [&](int k0) {
        #pragma unroll
        for (int r = 0; r < RA; r++) {
            int row = frow + 32 * r;
            int arow = min(bm + row, M - 1);
            pa[r] = *(const uint4*)&A[(size_t)arow * DIM_ + k0 + fcol];
        }
        #pragma unroll
        for (int r = 0; r < 4; r++) {
            int row = frow + 32 * r;
            pb[r] = *(const uint4*)&Wm[(size_t)(bn + row) * DIM_ + k0 + fcol];
        }
    };

    prefetch(0);

    for (int kc = 0; kc < 24; kc++) {
        uint32_t* As = gsm + (kc & 1) * ASZ;
        uint32_t* Bs = gsm + 2 * ASZ + (kc & 1) * BSZ;

        #pragma unroll
        for (int r = 0; r < RA; r++) {
            int row = frow + 32 * r;
            *(uint4*)&As[row * LDG_ + fcol] = pa[r];
        }
        #pragma unroll
        for (int r = 0; r < 4; r++) {
            int row = frow + 32 * r;
            *(uint4*)&Bs[row * LDG_ + fcol] = pb[r];
        }
        if (kc + 1 < 24) prefetch((kc + 1) * 32);
        __syncthreads();

        #pragma unroll
        for (int ks = 0; ks < 4; ks++) {
            const int kcc = ks * 8;
            uint32_t a0[4], a1[4];
            a0[0] = As[(ar +  0) * LDG_ + kcc + t];
            a0[1] = As[(ar +  8) * LDG_ + kcc + t];
            a0[2] = As[(ar +  0) * LDG_ + kcc + t + 4];
            a0[3] = As[(ar +  8) * LDG_ + kcc + t + 4];
            a1[0] = As[(ar + 16) * LDG_ + kcc + t];
            a1[1] = As[(ar + 24) * LDG_ + kcc + t];
            a1[2] = As[(ar + 16) * LDG_ + kcc + t + 4];
            a1[3] = As[(ar + 24) * LDG_ + kcc + t + 4];
            #pragma unroll
            for (int nt = 0; nt < NT; nt++) {
                uint32_t b[2];
                const int br = wc * (NT * 8) + nt * 8 + g;
                b[0] = Bs[br * LDG_ + kcc + t];
                b[1] = Bs[br * LDG_ + kcc + t + 4];
                mma_tf32(acc0[nt], a0, b);
                mma_tf32(acc1[nt], a1, b);
            }
        }
    }

    const int rows[4] = { bm + ar, bm + ar + 8, bm + ar + 16, bm + ar + 24 };
    #pragma unroll
    for (int nt = 0; nt < NT; nt++) {
        const int c0 = bn + wc * (NT * 8) + nt * 8 + 2 * t;
        float vals[4][2] = {
            {acc0[nt][0], acc0[nt][1]}, {acc0[nt][2], acc0[nt][3]},
            {acc1[nt][0], acc1[nt][1]}, {acc1[nt][2], acc1[nt][3]} };
        if (MODE == 0) {
            int which = c0 / DIM_;
            int rem = c0 - which * DIM_;
            int h = rem >> 6, d = rem & 63;
            float* dstf = (which == 0) ? g_Q : (which == 1) ? g_K : g_V;
            #pragma unroll
            for (int rr = 0; rr < 4; rr++) {
                int gm = rows[rr];
                if (gm < M) {
                    int b = gm / N_, n = gm - b * N_;
                    uint2 o = make_uint2(f2tf(vals[rr][0]), f2tf(vals[rr][1]));
                    *(uint2*)((uint32_t*)dstf +
                              (size_t)((b * H_ + h) * N_ + n) * HD_ + d) = o;
                }
            }
        } else {
            float bx = bias[c0], by = bias[c0 + 1];
            #pragma unroll
            for (int rr = 0; rr < 4; rr++) {
                int gm = rows[rr];
                if (gm < M) {
                    float2 o = make_float2(vals[rr][0] + bx, vals[rr][1] + by);
                    *(float2*)&out[(size_t)gm * DIM_ + c0] = o;
                }
            }
        }
    }
}

// ---------------------------------------------------------------------------
// cls scores (unroped, before rope)
// ---------------------------------------------------------------------------
__global__ void __launch_bounds__(256) cls_kernel() {
    int bh = blockIdx.x;
    int warp = threadIdx.x >> 5, lane = threadIdx.x & 31;
    int i = blockIdx.y * 8 + warp;
    if (i >= N_) return;
    const float2* Qi = (const float2*)(g_Q + ((size_t)bh * N_ + i) * HD_);
    const float2* K0 = (const float2*)(g_K + (size_t)bh * N_ * HD_);
    const float2* Q0 = (const float2*)(g_Q + (size_t)bh * N_ * HD_);
    const float2* Ki = (const float2*)(g_K + ((size_t)bh * N_ + i) * HD_);
    float2 a = Qi[lane], b0 = K0[lane], c = Q0[lane], d = Ki[lane];
    float s = a.x * b0.x + a.y * b0.y;
    float r = c.x * d.x + c.y * d.y;
    #pragma unroll
    for (int off = 16; off; off >>= 1) {
        s += __shfl_xor_sync(0xffffffffu, s, off);
        r += __shfl_xor_sync(0xffffffffu, r, off);
    }
    if (lane == 0) {
        g_col0[bh * N_ + i] = s;
        g_row0[bh * N_ + i] = r;
    }
}

// ---------------------------------------------------------------------------
// 2D RoPE in place on Q,K for n >= 1; outputs tf32-rounded
// ---------------------------------------------------------------------------
__global__ void rope_kernel(const int* __restrict__ xpos) {
    int b = blockIdx.x;
    int n = blockIdx.y + 1;
    int h = threadIdx.x >> 5;
    int lane = threadIdx.x & 31;
    int half = lane >> 4;
    int fi = lane & 15;
    float pos = (float)xpos[(b * N_ + n) * 2 + half];
    float inv = powf(100.f, -(float)fi / 16.f);
    float ang = pos * inv;
    float sv, cv;
    sincosf(ang, &sv, &cv);
    size_t base = ((size_t)(b * H_ + h) * N_ + n) * HD_ + half * 32;
    float t1 = g_Q[base + fi], t2 = g_Q[base + fi + 16];
    ((uint32_t*)g_Q)[base + fi]      = f2tf(t1 * cv - t2 * sv);
    ((uint32_t*)g_Q)[base + fi + 16] = f2tf(t2 * cv + t1 * sv);
    t1 = g_K[base + fi]; t2 = g_K[base + fi + 16];
    ((uint32_t*)g_K)[base + fi]      = f2tf(t1 * cv - t2 * sv);
    ((uint32_t*)g_K)[base + fi + 16] = f2tf(t2 * cv + t1 * sv);
}

// ---------------------------------------------------------------------------
// Flash attention (round-11 proven version, 540.4 us config): grid.y = 9,
// Q in smem, tile-specialized overrides, clamped guards.
// ---------------------------------------------------------------------------
constexpr int FLASH_SMEM = (128 * LD + 64 * LD + 64 * LDV + 128 * LD) * 4;  // 105472

__global__ void __launch_bounds__(128) flash_tf32_kernel() {
    extern __shared__ uint32_t sm[];
    uint32_t* Qs = sm;                    // [128][LD]
    uint32_t* Ks = Qs + 128 * LD;         // [64][LD]
    uint32_t* Vs = Ks + 64 * LD;          // [64][LDV]
    uint32_t* Ps = Vs + 64 * LDV;         // [128][LD]

    const uint32_t* Qg = (const uint32_t*)g_Q;
    const uint32_t* Kg = (const uint32_t*)g_K;
    const uint32_t* Vg = (const uint32_t*)g_V;

    const int bh = blockIdx.x;
    const int qbase = blockIdx.y * 128;
    const int tid = threadIdx.x;
    const int warp = tid >> 5, lane = tid & 31;
    const int g = lane >> 2, t = lane & 3;

    #pragma unroll
    for (int r = 0; r < 16; r++) {
        int idx = tid + 128 * r;
        int row = idx >> 4;
        int col = (idx & 15) << 2;
        int q = min(qbase + row, N_ - 1);
        *(uint4*)&Qs[row * LD + col] =
            *(const uint4*)&Qg[((size_t)bh * N_ + q) * HD_ + col];
    }

    float oacc0[8][4], oacc1[8][4];
    #pragma unroll
    for (int i = 0; i < 8; i++)
        #pragma unroll
        for (int j = 0; j < 4; j++) { oacc0[i][j] = 0.f; oacc1[i][j] = 0.f; }
    float m[4] = {-1e30f, -1e30f, -1e30f, -1e30f};
    float l[4] = {0.f, 0.f, 0.f, 0.f};

    const int pr0 = warp * 32 + g;
    const int rq[4] = { qbase + pr0, qbase + pr0 + 8,
                        qbase + pr0 + 16, qbase + pr0 + 24 };
    float colv[4];
    #pragma unroll
    for (int rr = 0; rr < 4; rr++) colv[rr] = g_col0[bh * N_ + min(rq[rr], N_ - 1)];
    const bool qzero = (rq[0] == 0);
    const float* rowp = g_row0 + bh * N_;

    for (int kt = 0; kt < 1088; kt += 64) {
        __syncthreads();
        #pragma unroll
        for (int r = 0; r < 8; r++) {
            int idx = tid + 128 * r;
            int row = idx >> 4;
            int col = (idx & 15) << 2;
            int k = kt + row;
            uint4 kv = make_uint4(0u, 0u, 0u, 0u);
            uint4 vv = make_uint4(0u, 0u, 0u, 0u);
            if (k < N_) {
                kv = *(const uint4*)&Kg[((size_t)bh * N_ + k) * HD_ + col];
                vv = *(const uint4*)&Vg[((size_t)bh * N_ + k) * HD_ + col];
            }
            *(uint4*)&Ks[row * LD + col] = kv;
            *(uint4*)&Vs[row * LDV + col] = vv;
        }
        __syncthreads();

        float sacc0[8][4], sacc1[8][4];
        #pragma unroll
        for (int i = 0; i < 8; i++)
            #pragma unroll
            for (int j = 0; j < 4; j++) { sacc0[i][j] = 0.f; sacc1[i][j] = 0.f; }

        #pragma unroll
        for (int ks = 0; ks < 8; ks++) {
            const int kc = ks * 8;
            uint32_t a0[4], a1[4];
            a0[0] = Qs[(pr0 +  0) * LD + kc + t];
            a0[1] = Qs[(pr0 +  8) * LD + kc + t];
            a0[2] = Qs[(pr0 +  0) * LD + kc + t + 4];
            a0[3] = Qs[(pr0 +  8) * LD + kc + t + 4];
            a1[0] = Qs[(pr0 + 16) * LD + kc + t];
            a1[1] = Qs[(pr0 + 24) * LD + kc + t];
            a1[2] = Qs[(pr0 + 16) * LD + kc + t + 4];
            a1[3] = Qs[(pr0 + 24) * LD + kc + t + 4];
            #pragma unroll
            for (int nt = 0; nt < 8; nt++) {
                uint32_t b[2];
                const int br = nt * 8 + g;
                b[0] = Ks[br * LD + kc + t];
                b[1] = Ks[br * LD + kc + t + 4];
                mma_tf32(sacc0[nt], a0, b);
                mma_tf32(sacc1[nt], a1, b);
            }
        }

        // ---- tile-specialized overrides ----
        if (kt == 1024) {
            #pragma unroll
            for (int nt = 0; nt < 8; nt++)
                #pragma unroll
                for (int c = 0; c < 4; c++) {
                    int kcol = kt + nt * 8 + 2 * t + (c & 1);
                    if (kcol >= N_) { sacc0[nt][c] = -1e30f; sacc1[nt][c] = -1e30f; }
                }
        }
        if (kt == 0 && t == 0) {
            sacc0[0][0] = colv[0]; sacc0[0][2] = colv[1];
            sacc1[0][0] = colv[2]; sacc1[0][2] = colv[3];
        }
        if (qzero) {
            #pragma unroll
            for (int nt = 0; nt < 8; nt++)
                #pragma unroll
                for (int c = 0; c < 2; c++) {
                    int kcol = kt + nt * 8 + 2 * t + c;
                    if (kcol < N_) sacc0[nt][c] = rowp[kcol];
                }
        }
        #pragma unroll
        for (int nt = 0; nt < 8; nt++)
            #pragma unroll
            for (int c = 0; c < 4; c++) { sacc0[nt][c] *= SCALE; sacc1[nt][c] *= SCALE; }
        // ------------------------------------

        #pragma unroll
        for (int hh = 0; hh < 4; hh++) {
            float (*sa)[4] = (hh < 2) ? sacc0 : sacc1;
            float (*oa)[4] = (hh < 2) ? oacc0 : oacc1;
            const int co = (hh & 1) * 2;
            float mx = -1e30f;
            #pragma unroll
            for (int nt = 0; nt < 8; nt++)
                mx = fmaxf(mx, fmaxf(sa[nt][co], sa[nt][co + 1]));
            mx = fmaxf(mx, __shfl_xor_sync(0xffffffffu, mx, 1));
            mx = fmaxf(mx, __shfl_xor_sync(0xffffffffu, mx, 2));
            float mn = fmaxf(m[hh], mx);
            float corr = __expf(m[hh] - mn);
            m[hh] = mn;
            float ls = 0.f;
            #pragma unroll
            for (int nt = 0; nt < 8; nt++) {
                float p0 = __expf(sa[nt][co] - mn);
                float p1 = __expf(sa[nt][co + 1] - mn);
                ls += p0 + p1;
                sa[nt][co] = p0;
                sa[nt][co + 1] = p1;
            }
            l[hh] = l[hh] * corr + ls;
            #pragma unroll
            for (int nt = 0; nt < 8; nt++) {
                oa[nt][co] *= corr;
                oa[nt][co + 1] *= corr;
            }
        }

        #pragma unroll
        for (int nt = 0; nt < 8; nt++) {
            int kc = nt * 8 + 2 * t;
            *(uint2*)&Ps[(pr0 +  0) * LD + kc] = make_uint2(f2tf(sacc0[nt][0]), f2tf(sacc0[nt][1]));
            *(uint2*)&Ps[(pr0 +  8) * LD + kc] = make_uint2(f2tf(sacc0[nt][2]), f2tf(sacc0[nt][3]));
            *(uint2*)&Ps[(pr0 + 16) * LD + kc] = make_uint2(f2tf(sacc1[nt][0]), f2tf(sacc1[nt][1]));
            *(uint2*)&Ps[(pr0 + 24) * LD + kc] = make_uint2(f2tf(sacc1[nt][2]), f2tf(sacc1[nt][3]));
        }
        __syncwarp();

        #pragma unroll
        for (int ks = 0; ks < 8; ks++) {
            const int kc = ks * 8;
            uint32_t a0[4], a1[4];
            a0[0] = Ps[(pr0 +  0) * LD + kc + t];
            a0[1] = Ps[(pr0 +  8) * LD + kc + t];
            a0[2] = Ps[(pr0 +  0) * LD + kc + t + 4];
            a0[3] = Ps[(pr0 +  8) * LD + kc + t + 4];
            a1[0] = Ps[(pr0 + 16) * LD + kc + t];
            a1[1] = Ps[(pr0 + 24) * LD + kc + t];
            a1[2] = Ps[(pr0 + 16) * LD + kc + t + 4];
            a1[3] = Ps[(pr0 + 24) * LD + kc + t + 4];
            #pragma unroll
            for (int nt = 0; nt < 8; nt++) {
                uint32_t b[2];
                b[0] = Vs[(kc + t) * LDV + nt * 8 + g];
                b[1] = Vs[(kc + t + 4) * LDV + nt * 8 + g];
                mma_tf32(oacc0[nt], a0, b);
                mma_tf32(oacc1[nt], a1, b);
            }
        }
    }

    #pragma unroll
    for (int hh = 0; hh < 4; hh++) {
        l[hh] += __shfl_xor_sync(0xffffffffu, l[hh], 1);
        l[hh] += __shfl_xor_sync(0xffffffffu, l[hh], 2);
        l[hh] = 1.f / l[hh];
    }
    const int b = bh / H_, h = bh - b * H_;
    uint32_t* att = (uint32_t*)g_att;
    #pragma unroll
    for (int nt = 0; nt < 8; nt++) {
        int d = nt * 8 + 2 * t;
        float vals[4][2] = {
            {oacc0[nt][0], oacc0[nt][1]}, {oacc0[nt][2], oacc0[nt][3]},
            {oacc1[nt][0], oacc1[nt][1]}, {oacc1[nt][2], oacc1[nt][3]} };
        #pragma unroll
        for (int rr = 0; rr < 4; rr++) {
            if (rq[rr] < N_) {
                uint2 o = make_uint2(f2tf(vals[rr][0] * l[rr]), f2tf(vals[rr][1] * l[rr]));
                *(uint2*)&att[((size_t)(b * N_ + rq[rr])) * DIM_ + h * HD_ + d] = o;
            }
        }
    }
}

// ---------------------------------------------------------------------------
constexpr int GEMM_SMEM0 = (2 * 128 * LDG_ + 2 * 128 * LDG_) * 4;  // 73728
constexpr int GEMM_SMEM1 = (2 * 64 * LDG_ + 2 * 128 * LDG_) * 4;   // 55296

extern "C" void kernel_launch(void* const* d_in, const int* in_sizes, int n_in,
                              void* d_out, int out_size) {
    int ix = -1, ixpos = -1, iwqkv = -1, iwproj = -1, ibproj = -1;
    for (int k = 0; k < n_in; k++) {
        switch (in_sizes[k]) {
            case NTOK * DIM_:  ix = k; break;
            case NTOK * 2:     ixpos = k; break;
            case C3 * DIM_:    iwqkv = k; break;
            case DIM_ * DIM_:  iwproj = k; break;
            case DIM_:         ibproj = k; break;
            default: break;
        }
    }
    const float* x      = (const float*)d_in[ix];
    const int*   xpos   = (const int*)d_in[ixpos];
    const float* w_qkv  = (const float*)d_in[iwqkv];
    const float* w_proj = (const float*)d_in[iwproj];
    const float* b_proj = (const float*)d_in[ibproj];
    float* out = (float*)d_out;

    cudaFuncSetAttribute((const void*)gemm_tf32_kernel<0, 128>,
                         cudaFuncAttributeMaxDynamicSharedMemorySize, GEMM_SMEM0);
    cudaFuncSetAttribute((const void*)gemm_tf32_kernel<1, 64>,
                         cudaFuncAttributeMaxDynamicSharedMemorySize, GEMM_SMEM1);
    cudaFuncSetAttribute(flash_tf32_kernel,
                         cudaFuncAttributeMaxDynamicSharedMemorySize, FLASH_SMEM);

    precvt_kernel<0><<<(NTOK * DIM_ / 4 + 255) / 256, 256>>>(x, NTOK * DIM_ / 4);
    precvt_kernel<1><<<(C3 * DIM_ / 4 + 255) / 256, 256>>>(w_qkv, C3 * DIM_ / 4);
    precvt_kernel<2><<<(DIM_ * DIM_ / 4 + 255) / 256, 256>>>(w_proj, DIM_ * DIM_ / 4);

    gemm_tf32_kernel<0, 128><<<dim3(C3 / 128, (NTOK + 127) / 128), 256, GEMM_SMEM0>>>(nullptr, nullptr, NTOK);
    cls_kernel<<<dim3(BH, (N_ + 7) / 8), 256>>>();
    rope_kernel<<<dim3(B_, N_ - 1), H_ * 32>>>(xpos);
    flash_tf32_kernel<<<dim3(BH, (N_ + 127) / 128), 128, FLASH_SMEM>>>();
    gemm_tf32_kernel<1, 64><<<dim3(DIM_ / 128, (NTOK + 63) / 64), 256, GEMM_SMEM1>>>(b_proj, out, NTOK);
}

// round 17
// speedup vs baseline: 1.1152x; 1.0225x over previous
#include <cuda_runtime.h>
#include <math.h>
#include <stdint.h>

// Problem constants
constexpr int B_   = 8;
constexpr int N_   = 1025;
constexpr int H_   = 12;
constexpr int HD_  = 64;
constexpr int DIM_ = 768;
constexpr int NTOK = B_ * N_;     // 8200
constexpr int C3   = 3 * DIM_;    // 2304
constexpr int BH   = B_ * H_;     // 96
constexpr float SCALE = 0.125f;

// Scratch (tf32-rounded-in-fp32 unless noted)
__device__ float g_Q[(size_t)BH * N_ * HD_];
__device__ float g_K[(size_t)BH * N_ * HD_];
__device__ float g_V[(size_t)BH * N_ * HD_];
__device__ float g_col0[BH * N_];              // fp32
__device__ float g_row0[BH * N_];              // fp32
__device__ float g_att[(size_t)NTOK * DIM_];
__device__ float g_xt[(size_t)NTOK * DIM_];
__device__ float g_wqkvt[C3 * DIM_];
__device__ float g_wprojt[DIM_ * DIM_];

// ---------------------------------------------------------------------------
__device__ __forceinline__ uint32_t f2tf(float f) {
    uint32_t u;
    asm("cvt.rna.tf32.f32 %0, %1;" : "=r"(u) : "f"(f));
    return u;
}

__device__ __forceinline__ void mma_tf32(float* d, const uint32_t* a, const uint32_t* b) {
    asm volatile(
        "mma.sync.aligned.m16n8k8.row.col.f32.tf32.tf32.f32 "
        "{%0,%1,%2,%3}, {%4,%5,%6,%7}, {%8,%9}, {%0,%1,%2,%3};\n"
        : "+f"(d[0]), "+f"(d[1]), "+f"(d[2]), "+f"(d[3])
        : "r"(a[0]), "r"(a[1]), "r"(a[2]), "r"(a[3]), "r"(b[0]), "r"(b[1]));
}

constexpr int LD   = 68;  // flash Q/K/P smem stride (words)
constexpr int LDV  = 72;  // flash V smem stride
constexpr int LDG_ = 36;  // GEMM smem stride (BK=32 + 4)

// ---------------------------------------------------------------------------
// Pre-round inputs to tf32 (once)
// ---------------------------------------------------------------------------
template <int W>
__global__ void precvt_kernel(const float* __restrict__ src, int n4) {
    int i = blockIdx.x * blockDim.x + threadIdx.x;
    if (i >= n4) return;
    float4 v = ((const float4*)src)[i];
    float* dst = (W == 0) ? g_xt : (W == 1) ? g_wqkvt : g_wprojt;
    ((uint4*)dst)[i] = make_uint4(f2tf(v.x), f2tf(v.y), f2tf(v.z), f2tf(v.w));
}

// ---------------------------------------------------------------------------
// tf32 GEMM (round-10 proven, 189 us): register prefetch + double-buffered
// smem, ONE sync per chunk. 256 threads = 8 warps (4x2), warp tile m32 x n64.
// ---------------------------------------------------------------------------
template <int MODE>
__global__ void __launch_bounds__(256, 2) gemm_tf32_kernel(const float* __restrict__ bias,
                                                           float* __restrict__ out,
                                                           int M) {
    extern __shared__ uint32_t gsm[];

    const uint32_t* A  = (MODE == 0) ? (const uint32_t*)g_xt   : (const uint32_t*)g_att;
    const uint32_t* Wm = (MODE == 0) ? (const uint32_t*)g_wqkvt : (const uint32_t*)g_wprojt;

    const int bm = blockIdx.y * 128;
    const int bn = blockIdx.x * 128;
    const int tid = threadIdx.x;
    const int warp = tid >> 5, lane = tid & 31;
    const int wr = warp >> 1, wc = warp & 1;
    const int g = lane >> 2, t = lane & 3;
    const int ar = wr * 32 + g;

    const int frow = tid >> 3;
    const int fcol = (tid & 7) << 2;

    float acc0[8][4], acc1[8][4];
    #pragma unroll
    for (int i = 0; i < 8; i++)
        #pragma unroll
        for (int j = 0; j < 4; j++) { acc0[i][j] = 0.f; acc1[i][j] = 0.f; }

    uint4 pa[4], pb[4];
    auto prefetch = [&](int k0) {
        #pragma unroll
        for (int r = 0; r < 4; r++) {
            int row = frow + 32 * r;
            int arow = min(bm + row, M - 1);
            pa[r] = *(const uint4*)&A[(size_t)arow * DIM_ + k0 + fcol];
            pb[r] = *(const uint4*)&Wm[(size_t)(bn + row) * DIM_ + k0 + fcol];
        }
    };

    prefetch(0);

    for (int kc = 0; kc < 24; kc++) {
        uint32_t* As = gsm + (kc & 1) * 4608;
        uint32_t* Bs = gsm + 9216 + (kc & 1) * 4608;

        #pragma unroll
        for (int r = 0; r < 4; r++) {
            int row = frow + 32 * r;
            *(uint4*)&As[row * LDG_ + fcol] = pa[r];
            *(uint4*)&Bs[row * LDG_ + fcol] = pb[r];
        }
        if (kc + 1 < 24) prefetch((kc + 1) * 32);
        __syncthreads();

        #pragma unroll
        for (int ks = 0; ks < 4; ks++) {
            const int kcc = ks * 8;
            uint32_t a0[4], a1[4];
            a0[0] = As[(ar +  0) * LDG_ + kcc + t];
            a0[1] = As[(ar +  8) * LDG_ + kcc + t];
            a0[2] = As[(ar +  0) * LDG_ + kcc + t + 4];
            a0[3] = As[(ar +  8) * LDG_ + kcc + t + 4];
            a1[0] = As[(ar + 16) * LDG_ + kcc + t];
            a1[1] = As[(ar + 24) * LDG_ + kcc + t];
            a1[2] = As[(ar + 16) * LDG_ + kcc + t + 4];
            a1[3] = As[(ar + 24) * LDG_ + kcc + t + 4];
            #pragma unroll
            for (int nt = 0; nt < 8; nt++) {
                uint32_t b[2];
                const int br = wc * 64 + nt * 8 + g;
                b[0] = Bs[br * LDG_ + kcc + t];
                b[1] = Bs[br * LDG_ + kcc + t + 4];
                mma_tf32(acc0[nt], a0, b);
                mma_tf32(acc1[nt], a1, b);
            }
        }
    }

    const int rows[4] = { bm + ar, bm + ar + 8, bm + ar + 16, bm + ar + 24 };
    #pragma unroll
    for (int nt = 0; nt < 8; nt++) {
        const int c0 = bn + wc * 64 + nt * 8 + 2 * t;
        float vals[4][2] = {
            {acc0[nt][0], acc0[nt][1]}, {acc0[nt][2], acc0[nt][3]},
            {acc1[nt][0], acc1[nt][1]}, {acc1[nt][2], acc1[nt][3]} };
        if (MODE == 0) {
            int which = c0 / DIM_;
            int rem = c0 - which * DIM_;
            int h = rem >> 6, d = rem & 63;
            float* dstf = (which == 0) ? g_Q : (which == 1) ? g_K : g_V;
            #pragma unroll
            for (int rr = 0; rr < 4; rr++) {
                int gm = rows[rr];
                if (gm < M) {
                    int b = gm / N_, n = gm - b * N_;
                    uint2 o = make_uint2(f2tf(vals[rr][0]), f2tf(vals[rr][1]));
                    *(uint2*)((uint32_t*)dstf +
                              (size_t)((b * H_ + h) * N_ + n) * HD_ + d) = o;
                }
            }
        } else {
            float bx = bias[c0], by = bias[c0 + 1];
            #pragma unroll
            for (int rr = 0; rr < 4; rr++) {
                int gm = rows[rr];
                if (gm < M) {
                    float2 o = make_float2(vals[rr][0] + bx, vals[rr][1] + by);
                    *(float2*)&out[(size_t)gm * DIM_ + c0] = o;
                }
            }
        }
    }
}

// ---------------------------------------------------------------------------
// cls scores (unroped, before rope)
// ---------------------------------------------------------------------------
__global__ void __launch_bounds__(256) cls_kernel() {
    int bh = blockIdx.x;
    int warp = threadIdx.x >> 5, lane = threadIdx.x & 31;
    int i = blockIdx.y * 8 + warp;
    if (i >= N_) return;
    const float2* Qi = (const float2*)(g_Q + ((size_t)bh * N_ + i) * HD_);
    const float2* K0 = (const float2*)(g_K + (size_t)bh * N_ * HD_);
    const float2* Q0 = (const float2*)(g_Q + (size_t)bh * N_ * HD_);
    const float2* Ki = (const float2*)(g_K + ((size_t)bh * N_ + i) * HD_);
    float2 a = Qi[lane], b0 = K0[lane], c = Q0[lane], d = Ki[lane];
    float s = a.x * b0.x + a.y * b0.y;
    float r = c.x * d.x + c.y * d.y;
    #pragma unroll
    for (int off = 16; off; off >>= 1) {
        s += __shfl_xor_sync(0xffffffffu, s, off);
        r += __shfl_xor_sync(0xffffffffu, r, off);
    }
    if (lane == 0) {
        g_col0[bh * N_ + i] = s;
        g_row0[bh * N_ + i] = r;
    }
}

// ---------------------------------------------------------------------------
// 2D RoPE in place on Q,K for n >= 1; outputs tf32-rounded
// ---------------------------------------------------------------------------
__global__ void rope_kernel(const int* __restrict__ xpos) {
    int b = blockIdx.x;
    int n = blockIdx.y + 1;
    int h = threadIdx.x >> 5;
    int lane = threadIdx.x & 31;
    int half = lane >> 4;
    int fi = lane & 15;
    float pos = (float)xpos[(b * N_ + n) * 2 + half];
    float inv = powf(100.f, -(float)fi / 16.f);
    float ang = pos * inv;
    float sv, cv;
    sincosf(ang, &sv, &cv);
    size_t base = ((size_t)(b * H_ + h) * N_ + n) * HD_ + half * 32;
    float t1 = g_Q[base + fi], t2 = g_Q[base + fi + 16];
    ((uint32_t*)g_Q)[base + fi]      = f2tf(t1 * cv - t2 * sv);
    ((uint32_t*)g_Q)[base + fi + 16] = f2tf(t2 * cv + t1 * sv);
    t1 = g_K[base + fi]; t2 = g_K[base + fi + 16];
    ((uint32_t*)g_K)[base + fi]      = f2tf(t1 * cv - t2 * sv);
    ((uint32_t*)g_K)[base + fi + 16] = f2tf(t2 * cv + t1 * sv);
}

// ---------------------------------------------------------------------------
// Flash attention (round-11 base): 16 full k-tiles (keys 0..1023, no guards)
// + peeled single-key epilogue for key 1024 (1 valid column).
// Numerically identical to the 17-tile version (masked slots contribute
// exact zeros; valid column accumulates in the same fragment order).
// ---------------------------------------------------------------------------
constexpr int FLASH_SMEM = (128 * LD + 64 * LD + 64 * LDV + 128 * LD) * 4;  // 105472

__global__ void __launch_bounds__(128) flash_tf32_kernel() {
    extern __shared__ uint32_t sm[];
    uint32_t* Qs = sm;                    // [128][LD]
    uint32_t* Ks = Qs + 128 * LD;         // [64][LD]
    uint32_t* Vs = Ks + 64 * LD;          // [64][LDV]
    uint32_t* Ps = Vs + 64 * LDV;         // [128][LD]

    const uint32_t* Qg = (const uint32_t*)g_Q;
    const uint32_t* Kg = (const uint32_t*)g_K;
    const uint32_t* Vg = (const uint32_t*)g_V;

    const int bh = blockIdx.x;
    const int qbase = blockIdx.y * 128;
    const int tid = threadIdx.x;
    const int warp = tid >> 5, lane = tid & 31;
    const int g = lane >> 2, t = lane & 3;

    #pragma unroll
    for (int r = 0; r < 16; r++) {
        int idx = tid + 128 * r;
        int row = idx >> 4;
        int col = (idx & 15) << 2;
        int q = min(qbase + row, N_ - 1);
        *(uint4*)&Qs[row * LD + col] =
            *(const uint4*)&Qg[((size_t)bh * N_ + q) * HD_ + col];
    }

    float oacc0[8][4], oacc1[8][4];
    #pragma unroll
    for (int i = 0; i < 8; i++)
        #pragma unroll
        for (int j = 0; j < 4; j++) { oacc0[i][j] = 0.f; oacc1[i][j] = 0.f; }
    float m[4] = {-1e30f, -1e30f, -1e30f, -1e30f};
    float l[4] = {0.f, 0.f, 0.f, 0.f};

    const int pr0 = warp * 32 + g;
    const int rq[4] = { qbase + pr0, qbase + pr0 + 8,
                        qbase + pr0 + 16, qbase + pr0 + 24 };
    float colv[4];
    #pragma unroll
    for (int rr = 0; rr < 4; rr++) colv[rr] = g_col0[bh * N_ + min(rq[rr], N_ - 1)];
    const bool qzero = (rq[0] == 0);
    const float* rowp = g_row0 + bh * N_;

    // -------- main loop: keys 0..1023 (all k-indices valid, no guards) ------
    for (int kt = 0; kt < 1024; kt += 64) {
        __syncthreads();
        #pragma unroll
        for (int r = 0; r < 8; r++) {
            int idx = tid + 128 * r;
            int row = idx >> 4;
            int col = (idx & 15) << 2;
            int k = kt + row;          // <= 1023 < N_
            *(uint4*)&Ks[row * LD + col] =
                *(const uint4*)&Kg[((size_t)bh * N_ + k) * HD_ + col];
            *(uint4*)&Vs[row * LDV + col] =
                *(const uint4*)&Vg[((size_t)bh * N_ + k) * HD_ + col];
        }
        __syncthreads();

        float sacc0[8][4], sacc1[8][4];
        #pragma unroll
        for (int i = 0; i < 8; i++)
            #pragma unroll
            for (int j = 0; j < 4; j++) { sacc0[i][j] = 0.f; sacc1[i][j] = 0.f; }

        #pragma unroll
        for (int ks = 0; ks < 8; ks++) {
            const int kc = ks * 8;
            uint32_t a0[4], a1[4];
            a0[0] = Qs[(pr0 +  0) * LD + kc + t];
            a0[1] = Qs[(pr0 +  8) * LD + kc + t];
            a0[2] = Qs[(pr0 +  0) * LD + kc + t + 4];
            a0[3] = Qs[(pr0 +  8) * LD + kc + t + 4];
            a1[0] = Qs[(pr0 + 16) * LD + kc + t];
            a1[1] = Qs[(pr0 + 24) * LD + kc + t];
            a1[2] = Qs[(pr0 + 16) * LD + kc + t + 4];
            a1[3] = Qs[(pr0 + 24) * LD + kc + t + 4];
            #pragma unroll
            for (int nt = 0; nt < 8; nt++) {
                uint32_t b[2];
                const int br = nt * 8 + g;
                b[0] = Ks[br * LD + kc + t];
                b[1] = Ks[br * LD + kc + t + 4];
                mma_tf32(sacc0[nt], a0, b);
                mma_tf32(sacc1[nt], a1, b);
            }
        }

        // ---- tile-specialized overrides (no masking needed here) ----
        if (kt == 0 && t == 0) {
            sacc0[0][0] = colv[0]; sacc0[0][2] = colv[1];
            sacc1[0][0] = colv[2]; sacc1[0][2] = colv[3];
        }
        if (qzero) {
            #pragma unroll
            for (int nt = 0; nt < 8; nt++)
                #pragma unroll
                for (int c = 0; c < 2; c++) {
                    int kcol = kt + nt * 8 + 2 * t + c;   // <= 1023
                    sacc0[nt][c] = rowp[kcol];
                }
        }
        #pragma unroll
        for (int nt = 0; nt < 8; nt++)
            #pragma unroll
            for (int c = 0; c < 4; c++) { sacc0[nt][c] *= SCALE; sacc1[nt][c] *= SCALE; }
        // --------------------------------------------------------------

        #pragma unroll
        for (int hh = 0; hh < 4; hh++) {
            float (*sa)[4] = (hh < 2) ? sacc0 : sacc1;
            float (*oa)[4] = (hh < 2) ? oacc0 : oacc1;
            const int co = (hh & 1) * 2;
            float mx = -1e30f;
            #pragma unroll
            for (int nt = 0; nt < 8; nt++)
                mx = fmaxf(mx, fmaxf(sa[nt][co], sa[nt][co + 1]));
            mx = fmaxf(mx, __shfl_xor_sync(0xffffffffu, mx, 1));
            mx = fmaxf(mx, __shfl_xor_sync(0xffffffffu, mx, 2));
            float mn = fmaxf(m[hh], mx);
            float corr = __expf(m[hh] - mn);
            m[hh] = mn;
            float ls = 0.f;
            #pragma unroll
            for (int nt = 0; nt < 8; nt++) {
                float p0 = __expf(sa[nt][co] - mn);
                float p1 = __expf(sa[nt][co + 1] - mn);
                ls += p0 + p1;
                sa[nt][co] = p0;
                sa[nt][co + 1] = p1;
            }
            l[hh] = l[hh] * corr + ls;
            #pragma unroll
            for (int nt = 0; nt < 8; nt++) {
                oa[nt][co] *= corr;
                oa[nt][co + 1] *= corr;
            }
        }

        #pragma unroll
        for (int nt = 0; nt < 8; nt++) {
            int kc = nt * 8 + 2 * t;
            *(uint2*)&Ps[(pr0 +  0) * LD + kc] = make_uint2(f2tf(sacc0[nt][0]), f2tf(sacc0[nt][1]));
            *(uint2*)&Ps[(pr0 +  8) * LD + kc] = make_uint2(f2tf(sacc0[nt][2]), f2tf(sacc0[nt][3]));
            *(uint2*)&Ps[(pr0 + 16) * LD + kc] = make_uint2(f2tf(sacc1[nt][0]), f2tf(sacc1[nt][1]));
            *(uint2*)&Ps[(pr0 + 24) * LD + kc] = make_uint2(f2tf(sacc1[nt][2]), f2tf(sacc1[nt][3]));
        }
        __syncwarp();

        #pragma unroll
        for (int ks = 0; ks < 8; ks++) {
            const int kc = ks * 8;
            uint32_t a0[4], a1[4];
            a0[0] = Ps[(pr0 +  0) * LD + kc + t];
            a0[1] = Ps[(pr0 +  8) * LD + kc + t];
            a0[2] = Ps[(pr0 +  0) * LD + kc + t + 4];
            a0[3] = Ps[(pr0 +  8) * LD + kc + t + 4];
            a1[0] = Ps[(pr0 + 16) * LD + kc + t];
            a1[1] = Ps[(pr0 + 24) * LD + kc + t];
            a1[2] = Ps[(pr0 + 16) * LD + kc + t + 4];
            a1[3] = Ps[(pr0 + 24) * LD + kc + t + 4];
            #pragma unroll
            for (int nt = 0; nt < 8; nt++) {
                uint32_t b[2];
                b[0] = Vs[(kc + t) * LDV + nt * 8 + g];
                b[1] = Vs[(kc + t + 4) * LDV + nt * 8 + g];
                mma_tf32(oacc0[nt], a0, b);
                mma_tf32(oacc1[nt], a1, b);
            }
        }
    }

    // -------- peeled final key (k = 1024): one k8 group --------------------
    __syncthreads();   // last tile's Ks/Vs reads done
    for (int i = tid; i < 7 * LD; i += 128) Ks[LD + i] = 0u;       // rows 1..7
    for (int i = tid; i < 7 * LDV; i += 128) Vs[LDV + i] = 0u;
    if (tid < 16) {
        int col = tid * 4;
        *(uint4*)&Ks[col] = *(const uint4*)&Kg[((size_t)bh * N_ + 1024) * HD_ + col];
        *(uint4*)&Vs[col] = *(const uint4*)&Vg[((size_t)bh * N_ + 1024) * HD_ + col];
    }
    __syncthreads();

    {
        float s0[4] = {0.f, 0.f, 0.f, 0.f}, s1[4] = {0.f, 0.f, 0.f, 0.f};
        #pragma unroll
        for (int ks = 0; ks < 8; ks++) {
            const int kc = ks * 8;
            uint32_t a0[4], a1[4];
            a0[0] = Qs[(pr0 +  0) * LD + kc + t];
            a0[1] = Qs[(pr0 +  8) * LD + kc + t];
            a0[2] = Qs[(pr0 +  0) * LD + kc + t + 4];
            a0[3] = Qs[(pr0 +  8) * LD + kc + t + 4];
            a1[0] = Qs[(pr0 + 16) * LD + kc + t];
            a1[1] = Qs[(pr0 + 24) * LD + kc + t];
            a1[2] = Qs[(pr0 + 16) * LD + kc + t + 4];
            a1[3] = Qs[(pr0 + 24) * LD + kc + t + 4];
            uint32_t b[2];
            b[0] = Ks[g * LD + kc + t];
            b[1] = Ks[g * LD + kc + t + 4];
            mma_tf32(s0, a0, b);
            mma_tf32(s1, a1, b);
        }
        // only (t==0, c in {0,2}) holds kcol==1024; qzero row uses rowp[1024]
        float v00 = (qzero ? rowp[1024] : s0[0]) * SCALE;
        float v02 = s0[2] * SCALE;
        float v10 = s1[0] * SCALE;
        float v12 = s1[2] * SCALE;
        s0[0] = (t == 0) ? v00 : -1e30f;  s0[1] = -1e30f;
        s0[2] = (t == 0) ? v02 : -1e30f;  s0[3] = -1e30f;
        s1[0] = (t == 0) ? v10 : -1e30f;  s1[1] = -1e30f;
        s1[2] = (t == 0) ? v12 : -1e30f;  s1[3] = -1e30f;

        #pragma unroll
        for (int hh = 0; hh < 4; hh++) {
            float* sa = (hh < 2) ? s0 : s1;
            float (*oa)[4] = (hh < 2) ? oacc0 : oacc1;
            const int co = (hh & 1) * 2;
            float mx = fmaxf(sa[co], sa[co + 1]);
            mx = fmaxf(mx, __shfl_xor_sync(0xffffffffu, mx, 1));
            mx = fmaxf(mx, __shfl_xor_sync(0xffffffffu, mx, 2));
            float mn = fmaxf(m[hh], mx);
            float corr = __expf(m[hh] - mn);
            m[hh] = mn;
            float p0 = __expf(sa[co] - mn);
            float p1 = __expf(sa[co + 1] - mn);
            l[hh] = l[hh] * corr + p0 + p1;
            sa[co] = p0;
            sa[co + 1] = p1;
            #pragma unroll
            for (int nt = 0; nt < 8; nt++) {
                oa[nt][co] *= corr;
                oa[nt][co + 1] *= corr;
            }
        }

        *(uint2*)&Ps[(pr0 +  0) * LD + 2 * t] = make_uint2(f2tf(s0[0]), f2tf(s0[1]));
        *(uint2*)&Ps[(pr0 +  8) * LD + 2 * t] = make_uint2(f2tf(s0[2]), f2tf(s0[3]));
        *(uint2*)&Ps[(pr0 + 16) * LD + 2 * t] = make_uint2(f2tf(s1[0]), f2tf(s1[1]));
        *(uint2*)&Ps[(pr0 + 24) * LD + 2 * t] = make_uint2(f2tf(s1[2]), f2tf(s1[3]));
        __syncwarp();

        uint32_t a0[4], a1[4];
        a0[0] = Ps[(pr0 +  0) * LD + t];
        a0[1] = Ps[(pr0 +  8) * LD + t];
        a0[2] = Ps[(pr0 +  0) * LD + t + 4];
        a0[3] = Ps[(pr0 +  8) * LD + t + 4];
        a1[0] = Ps[(pr0 + 16) * LD + t];
        a1[1] = Ps[(pr0 + 24) * LD + t];
        a1[2] = Ps[(pr0 + 16) * LD + t + 4];
        a1[3] = Ps[(pr0 + 24) * LD + t + 4];
        #pragma unroll
        for (int nt = 0; nt < 8; nt++) {
            uint32_t b[2];
            b[0] = Vs[t * LDV + nt * 8 + g];
            b[1] = Vs[(t + 4) * LDV + nt * 8 + g];
            mma_tf32(oacc0[nt], a0, b);
            mma_tf32(oacc1[nt], a1, b);
        }
    }

    // -------- finalize ------------------------------------------------------
    #pragma unroll
    for (int hh = 0; hh < 4; hh++) {
        l[hh] += __shfl_xor_sync(0xffffffffu, l[hh], 1);
        l[hh] += __shfl_xor_sync(0xffffffffu, l[hh], 2);
        l[hh] = 1.f / l[hh];
    }
    const int b = bh / H_, h = bh - b * H_;
    uint32_t* att = (uint32_t*)g_att;
    #pragma unroll
    for (int nt = 0; nt < 8; nt++) {
        int d = nt * 8 + 2 * t;
        float vals[4][2] = {
            {oacc0[nt][0], oacc0[nt][1]}, {oacc0[nt][2], oacc0[nt][3]},
            {oacc1[nt][0], oacc1[nt][1]}, {oacc1[nt][2], oacc1[nt][3]} };
        #pragma unroll
        for (int rr = 0; rr < 4; rr++) {
            if (rq[rr] < N_) {
                uint2 o = make_uint2(f2tf(vals[rr][0] * l[rr]), f2tf(vals[rr][1] * l[rr]));
                *(uint2*)&att[((size_t)(b * N_ + rq[rr])) * DIM_ + h * HD_ + d] = o;
            }
        }
    }
}

// ---------------------------------------------------------------------------
constexpr int GEMM_SMEM = 4 * 4608 * 4;   // 73728

extern "C" void kernel_launch(void* const* d_in, const int* in_sizes, int n_in,
                              void* d_out, int out_size) {
    int ix = -1, ixpos = -1, iwqkv = -1, iwproj = -1, ibproj = -1;
    for (int k = 0; k < n_in; k++) {
        switch (in_sizes[k]) {
            case NTOK * DIM_:  ix = k; break;
            case NTOK * 2:     ixpos = k; break;
            case C3 * DIM_:    iwqkv = k; break;
            case DIM_ * DIM_:  iwproj = k; break;
            case DIM_:         ibproj = k; break;
            default: break;
        }
    }
    const float* x      = (const float*)d_in[ix];
    const int*   xpos   = (const int*)d_in[ixpos];
    const float* w_qkv  = (const float*)d_in[iwqkv];
    const float* w_proj = (const float*)d_in[iwproj];
    const float* b_proj = (const float*)d_in[ibproj];
    float* out = (float*)d_out;

    cudaFuncSetAttribute(gemm_tf32_kernel<0>, cudaFuncAttributeMaxDynamicSharedMemorySize, GEMM_SMEM);
    cudaFuncSetAttribute(gemm_tf32_kernel<1>, cudaFuncAttributeMaxDynamicSharedMemorySize, GEMM_SMEM);
    cudaFuncSetAttribute(flash_tf32_kernel,   cudaFuncAttributeMaxDynamicSharedMemorySize, FLASH_SMEM);

    const int mtiles = (NTOK + 127) / 128;   // 65

    precvt_kernel<0><<<(NTOK * DIM_ / 4 + 255) / 256, 256>>>(x, NTOK * DIM_ / 4);
    precvt_kernel<1><<<(C3 * DIM_ / 4 + 255) / 256, 256>>>(w_qkv, C3 * DIM_ / 4);
    precvt_kernel<2><<<(DIM_ * DIM_ / 4 + 255) / 256, 256>>>(w_proj, DIM_ * DIM_ / 4);

    gemm_tf32_kernel<0><<<dim3(C3 / 128, mtiles), 256, GEMM_SMEM>>>(nullptr, nullptr, NTOK);
    cls_kernel<<<dim3(BH, (N_ + 7) / 8), 256>>>();
    rope_kernel<<<dim3(B_, N_ - 1), H_ * 32>>>(xpos);
    flash_tf32_kernel<<<dim3(BH, (N_ + 127) / 128), 128, FLASH_SMEM>>>();
    gemm_tf32_kernel<1><<<dim3(DIM_ / 128, mtiles), 256, GEMM_SMEM>>>(b_proj, out, NTOK);
}